// round 2
// baseline (speedup 1.0000x reference)
#include <cuda_runtime.h>
#include <math.h>
#include <stdint.h>

#define BATCH 8
#define CIN   512
#define CK    256
#define CV    256
#define COUT  512
#define NPIX  16384
#define PTOK  19
#define BN_EPS 1e-5f

// ---------------- scratch (static device memory; no allocations) ----------------
__device__ __align__(16) float g_k1[BATCH * CK * NPIX];     // fk proj (pre-BN), [b][k][n]
__device__ __align__(16) float g_q2[BATCH * CK * NPIX];     // fq proj (pre-BN), [b][k][n]
__device__ __align__(16) float g_v1[BATCH * CV * NPIX];     // fv proj (+bias),  [b][v][n]
__device__ __align__(16) float g_logits1[BATCH * PTOK * NPIX]; // stage1 logits -> probs, [b][p][n]
__device__ __align__(16) float g_sim2[BATCH * PTOK * NPIX];    // stage2 probs, [b][p][n]
__device__ __align__(16) float g_ctx[BATCH * PTOK * CV];       // proxy context, [b][p][v]
__device__ __align__(16) float g_M[BATCH * COUT * 20];         // M[o][p] padded to 20, per batch
__device__ float g_q1[CK * PTOK];   // post-BN lrelu, [k][p]
__device__ float g_k2[CK * PTOK];   // post-BN lrelu, [k][p]
__device__ float g_stat[4 * CK];    // ksum | ksumsq | qsum | qsumsq
__device__ float g_kscale[CK], g_kshift[CK], g_qscale[CK], g_qshift[CK];

// ---------------- init: zero atomically-accumulated buffers ----------------
__global__ void kInit() {
    int i = blockIdx.x * blockDim.x + threadIdx.x;
    if (i < 4 * CK) g_stat[i] = 0.0f;
    int j = i - 4 * CK;
    if (j >= 0 && j < BATCH * PTOK * CV) g_ctx[j] = 0.0f;
}

// ---------------- Pass A: fused projection GEMM ----------------
// For batch b: y[m,n] = sum_c W[m,c] * x[b,c,n] + bias[m]
// M = 768 stacked rows: [0,256)=fk -> g_k1, [256,512)=fq -> g_q2, [512,768)=fv -> g_v1
__global__ __launch_bounds__(256) void kA(
    const float* __restrict__ x,
    const float* __restrict__ fk_w, const float* __restrict__ fk_b,
    const float* __restrict__ fq_w, const float* __restrict__ fq_b,
    const float* __restrict__ fv_w, const float* __restrict__ fv_b)
{
    __shared__ __align__(16) float As[16][132];
    __shared__ __align__(16) float Bs[16][132];

    const int bx = blockIdx.x;       // n tile (128 wide)
    const int by = blockIdx.y;       // m tile (128 tall), 0..5
    const int b  = blockIdx.z;
    const int tid = threadIdx.x;

    const float* wptr; const float* bptr; float* dst;
    if (by < 2)      { wptr = fk_w; bptr = fk_b; dst = g_k1; }
    else if (by < 4) { wptr = fq_w; bptr = fq_b; dst = g_q2; }
    else             { wptr = fv_w; bptr = fv_b; dst = g_v1; }
    const int mrow0 = (by & 1) * 128;
    const int n0 = bx * 128;
    const float* xb = x + (size_t)b * CIN * NPIX;

    float acc[8][8];
#pragma unroll
    for (int i = 0; i < 8; i++)
#pragma unroll
        for (int j = 0; j < 8; j++) acc[i][j] = 0.0f;

    const int tm = tid >> 4;   // 0..15
    const int tn = tid & 15;   // 0..15

    for (int k0 = 0; k0 < CIN; k0 += 16) {
        // load A tile (128 m x 16 k), transposed into As[k][m]
#pragma unroll
        for (int it = 0; it < 2; it++) {
            int s = tid + it * 256;
            int m = s >> 2, kq = (s & 3) * 4;
            float4 a = *(const float4*)&wptr[(size_t)(mrow0 + m) * CIN + k0 + kq];
            As[kq + 0][m] = a.x; As[kq + 1][m] = a.y;
            As[kq + 2][m] = a.z; As[kq + 3][m] = a.w;
        }
        // load B tile (16 k x 128 n)
#pragma unroll
        for (int it = 0; it < 2; it++) {
            int s = tid + it * 256;
            int k = s >> 5, nq = (s & 31) * 4;
            *(float4*)&Bs[k][nq] = *(const float4*)&xb[(size_t)(k0 + k) * NPIX + n0 + nq];
        }
        __syncthreads();
#pragma unroll
        for (int k = 0; k < 16; k++) {
            float ar[8], br[8];
            *(float4*)&ar[0] = *(const float4*)&As[k][tm * 8];
            *(float4*)&ar[4] = *(const float4*)&As[k][tm * 8 + 4];
            *(float4*)&br[0] = *(const float4*)&Bs[k][tn * 8];
            *(float4*)&br[4] = *(const float4*)&Bs[k][tn * 8 + 4];
#pragma unroll
            for (int i = 0; i < 8; i++)
#pragma unroll
                for (int j = 0; j < 8; j++) acc[i][j] = fmaf(ar[i], br[j], acc[i][j]);
        }
        __syncthreads();
    }
    const size_t outbase = (size_t)b * CK * NPIX;
#pragma unroll
    for (int i = 0; i < 8; i++) {
        int ch = mrow0 + tm * 8 + i;
        float bias = bptr[ch];
        float* row = dst + outbase + (size_t)ch * NPIX + n0 + tn * 8;
        float4 r0, r1;
        r0.x = acc[i][0] + bias; r0.y = acc[i][1] + bias;
        r0.z = acc[i][2] + bias; r0.w = acc[i][3] + bias;
        r1.x = acc[i][4] + bias; r1.y = acc[i][5] + bias;
        r1.z = acc[i][6] + bias; r1.w = acc[i][7] + bias;
        *(float4*)&row[0] = r0;
        *(float4*)&row[4] = r1;
    }
}

// ---------------- BN stats over (b, n) per channel for k1 and q2 ----------------
__global__ __launch_bounds__(256) void kStats() {
    const int ch = blockIdx.x;          // 0..511 : [0,256)=k, [256,512)=q
    const int chunk = blockIdx.y;       // 0..15
    const float* src = (ch < CK) ? g_k1 : g_q2;
    const int c = ch & (CK - 1);
    const int b = chunk >> 1;
    const int nh = (chunk & 1) * (NPIX / 2);
    const float* base = src + ((size_t)b * CK + c) * NPIX + nh;
    float sum = 0.0f, sq = 0.0f;
    for (int i = threadIdx.x; i < NPIX / 2; i += 256) {
        float v = base[i];
        sum += v; sq += v * v;
    }
    __shared__ float s1[256], s2[256];
    s1[threadIdx.x] = sum; s2[threadIdx.x] = sq;
    __syncthreads();
    for (int off = 128; off > 0; off >>= 1) {
        if (threadIdx.x < off) {
            s1[threadIdx.x] += s1[threadIdx.x + off];
            s2[threadIdx.x] += s2[threadIdx.x + off];
        }
        __syncthreads();
    }
    if (threadIdx.x == 0) {
        int b2 = (ch < CK) ? 0 : 2 * CK;
        atomicAdd(&g_stat[b2 + c], s1[0]);
        atomicAdd(&g_stat[b2 + CK + c], s2[0]);
    }
}

// ---------------- finalize BN scale/shift ----------------
__global__ void kFin(const float* __restrict__ fk_g, const float* __restrict__ fk_beta,
                     const float* __restrict__ fq_g, const float* __restrict__ fq_beta) {
    int t = threadIdx.x;  // 512 threads
    const float inv = 1.0f / (float)(BATCH * NPIX);
    if (t < CK) {
        float mean = g_stat[t] * inv;
        float var = g_stat[CK + t] * inv - mean * mean;
        float sc = fk_g[t] * rsqrtf(var + BN_EPS);
        g_kscale[t] = sc;
        g_kshift[t] = fk_beta[t] - mean * sc;
    } else if (t < 2 * CK) {
        int c = t - CK;
        float mean = g_stat[2 * CK + c] * inv;
        float var = g_stat[3 * CK + c] * inv - mean * mean;
        float sc = fq_g[c] * rsqrtf(var + BN_EPS);
        g_qscale[c] = sc;
        g_qshift[c] = fq_beta[c] - mean * sc;
    }
}

// ---------------- tiny proxy-side projections: q1 and k2 (BN over P=19) ----------------
__global__ __launch_bounds__(256) void kT(
    const float* __restrict__ proxy,
    const float* __restrict__ pq_w, const float* __restrict__ pq_b,
    const float* __restrict__ pq_g, const float* __restrict__ pq_beta,
    const float* __restrict__ pk_w, const float* __restrict__ pk_b,
    const float* __restrict__ pk_g, const float* __restrict__ pk_beta)
{
    __shared__ float sp[CIN * PTOK];
    for (int i = threadIdx.x; i < CIN * PTOK; i += 256) sp[i] = proxy[i];
    __syncthreads();
    const int k = threadIdx.x;  // one channel per thread
    for (int which = 0; which < 2; which++) {
        const float* w  = which ? pk_w : pq_w;
        const float* bb = which ? pk_b : pq_b;
        const float* g  = which ? pk_g : pq_g;
        const float* be = which ? pk_beta : pq_beta;
        float* dst = which ? g_k2 : g_q1;
        float acc[PTOK];
#pragma unroll
        for (int p = 0; p < PTOK; p++) acc[p] = bb[k];
        for (int c = 0; c < CIN; c++) {
            float wv = w[(size_t)k * CIN + c];
#pragma unroll
            for (int p = 0; p < PTOK; p++) acc[p] = fmaf(wv, sp[c * PTOK + p], acc[p]);
        }
        float mean = 0.0f;
#pragma unroll
        for (int p = 0; p < PTOK; p++) mean += acc[p];
        mean *= (1.0f / PTOK);
        float var = 0.0f;
#pragma unroll
        for (int p = 0; p < PTOK; p++) { float d = acc[p] - mean; var += d * d; }
        var *= (1.0f / PTOK);
        float sc = g[k] * rsqrtf(var + BN_EPS);
        float sh = be[k] - mean * sc;
#pragma unroll
        for (int p = 0; p < PTOK; p++) {
            float z = acc[p] * sc + sh;
            dst[k * PTOK + p] = (z > 0.0f) ? z : 0.01f * z;
        }
    }
}

// ---------------- stage 1 logits: L[b,p,n] = sum_k q1[k,p] * lrelu(BN(k1[b,k,n])) ----------------
__global__ __launch_bounds__(256) void kB1() {
    __shared__ float q1s[CK * PTOK];
    __shared__ float ks[CK], kh[CK];
    const int b = blockIdx.y;
    const int n = blockIdx.x * 256 + threadIdx.x;
    for (int i = threadIdx.x; i < CK * PTOK; i += 256) q1s[i] = g_q1[i];
    if (threadIdx.x < CK) { ks[threadIdx.x] = g_kscale[threadIdx.x]; kh[threadIdx.x] = g_kshift[threadIdx.x]; }
    __syncthreads();
    float acc[PTOK];
#pragma unroll
    for (int p = 0; p < PTOK; p++) acc[p] = 0.0f;
    const float* kp = g_k1 + (size_t)b * CK * NPIX + n;
    for (int k = 0; k < CK; k++) {
        float v = kp[(size_t)k * NPIX];
        v = fmaf(v, ks[k], kh[k]);
        v = (v > 0.0f) ? v : 0.01f * v;
#pragma unroll
        for (int p = 0; p < PTOK; p++) acc[p] = fmaf(q1s[k * PTOK + p], v, acc[p]);
    }
    float* out = g_logits1 + (size_t)b * PTOK * NPIX + n;
#pragma unroll
    for (int p = 0; p < PTOK; p++) out[(size_t)p * NPIX] = acc[p];
}

// ---------------- stage 1 softmax over N (in place) ----------------
__global__ __launch_bounds__(256) void kB2() {
    const int p = blockIdx.x, b = blockIdx.y;
    float* row = g_logits1 + ((size_t)b * PTOK + p) * NPIX;
    __shared__ float red[256];
    const int tid = threadIdx.x;
    float m = -3.4e38f;
    for (int i = tid; i < NPIX; i += 256) m = fmaxf(m, row[i]);
    red[tid] = m; __syncthreads();
    for (int off = 128; off > 0; off >>= 1) {
        if (tid < off) red[tid] = fmaxf(red[tid], red[tid + off]);
        __syncthreads();
    }
    float mx = red[0];
    __syncthreads();
    float s = 0.0f;
    for (int i = tid; i < NPIX; i += 256) s += expf(row[i] - mx);
    red[tid] = s; __syncthreads();
    for (int off = 128; off > 0; off >>= 1) {
        if (tid < off) red[tid] += red[tid + off];
        __syncthreads();
    }
    float inv = 1.0f / red[0];
    for (int i = tid; i < NPIX; i += 256) row[i] = expf(row[i] - mx) * inv;
}

// ---------------- stage 1 context: ctx[b,p,v] = sum_n sim1[b,p,n] * v1[b,v,n] ----------------
__global__ __launch_bounds__(256) void kB3() {
    __shared__ float vs[64 * 129];
    __shared__ float ss[PTOK * 129];
    const int nch = blockIdx.x;   // 0..7, 2048 n each
    const int vt  = blockIdx.y;   // 0..3, 64 v each
    const int b   = blockIdx.z;
    const int v0 = vt * 64;
    const int tid = threadIdx.x;
    const int tx16 = tid & 15;          // v group (4 v each)
    const int ty   = (tid >> 4) & 3;    // p group (5 p each)
    const int tz   = tid >> 6;          // nn quarter
    float acc[4][5];
#pragma unroll
    for (int i = 0; i < 4; i++)
#pragma unroll
        for (int j = 0; j < 5; j++) acc[i][j] = 0.0f;

    const float* vbase = g_v1 + ((size_t)b * CV + v0) * NPIX;
    const float* sbase = g_logits1 + (size_t)b * PTOK * NPIX;

    for (int st = 0; st < 16; st++) {
        const int nb = nch * 2048 + st * 128;
        for (int s = tid; s < 64 * 128; s += 256) {
            int r = s >> 7, c = s & 127;
            vs[r * 129 + c] = vbase[(size_t)r * NPIX + nb + c];
        }
        for (int s = tid; s < PTOK * 128; s += 256) {
            int r = s >> 7, c = s & 127;
            ss[r * 129 + c] = sbase[(size_t)r * NPIX + nb + c];
        }
        __syncthreads();
#pragma unroll 4
        for (int nn = tz * 32; nn < tz * 32 + 32; nn++) {
            float sv[5];
#pragma unroll
            for (int j = 0; j < 5; j++) {
                int p = ty * 5 + j;
                sv[j] = (p < PTOK) ? ss[p * 129 + nn] : 0.0f;
            }
#pragma unroll
            for (int i = 0; i < 4; i++) {
                float vv = vs[(tx16 * 4 + i) * 129 + nn];
#pragma unroll
                for (int j = 0; j < 5; j++) acc[i][j] = fmaf(vv, sv[j], acc[i][j]);
            }
        }
        __syncthreads();
    }
#pragma unroll
    for (int j = 0; j < 5; j++) {
        int p = ty * 5 + j;
        if (p < PTOK) {
#pragma unroll
            for (int i = 0; i < 4; i++)
                atomicAdd(&g_ctx[((size_t)b * PTOK + p) * CV + v0 + tx16 * 4 + i], acc[i][j]);
        }
    }
}

// ---------------- M precompute: M[b,o,p] = sum_v W[o,v] * ctx[b,p,v] ----------------
__global__ __launch_bounds__(256) void kM(const float* __restrict__ Ww) {
    __shared__ float ctxs[PTOK * CV];
    const int b = blockIdx.x;
    for (int i = threadIdx.x; i < PTOK * CV; i += 256)
        ctxs[i] = g_ctx[(size_t)b * PTOK * CV + i];
    __syncthreads();
    for (int rep = 0; rep < 2; rep++) {
        int o = rep * 256 + threadIdx.x;
        float acc[PTOK];
#pragma unroll
        for (int p = 0; p < PTOK; p++) acc[p] = 0.0f;
        for (int v = 0; v < CV; v++) {
            float w = Ww[(size_t)o * CV + v];
#pragma unroll
            for (int p = 0; p < PTOK; p++) acc[p] = fmaf(w, ctxs[p * CV + v], acc[p]);
        }
        float* dst = &g_M[((size_t)b * COUT + o) * 20];
#pragma unroll
        for (int p = 0; p < PTOK; p++) dst[p] = acc[p];
        dst[19] = 0.0f;
    }
}

// ---------------- stage 2: logits + softmax over P=19, fused BN/lrelu on q2 ----------------
__global__ __launch_bounds__(256) void kC1() {
    __shared__ float k2s[CK * PTOK];
    __shared__ float q2s[16 * 132];
    __shared__ float L[PTOK * 132];
    __shared__ float qs[CK], qh[CK];
    const int b = blockIdx.y;
    const int n0 = blockIdx.x * 128;
    const int tid = threadIdx.x;
    const int nl = tid & 127;
    const int half = tid >> 7;
    for (int i = tid; i < CK * PTOK; i += 256) k2s[i] = g_k2[i];
    if (tid < CK) { qs[tid] = g_qscale[tid]; qh[tid] = g_qshift[tid]; }
    __syncthreads();
    const int p0 = half * 10;
    const int nj = half ? 9 : 10;
    float acc[10];
#pragma unroll
    for (int j = 0; j < 10; j++) acc[j] = 0.0f;
    const float* qb = g_q2 + (size_t)b * CK * NPIX + n0;
    for (int k0 = 0; k0 < CK; k0 += 16) {
        for (int s = tid; s < 16 * 128; s += 256) {
            int r = s >> 7, c = s & 127;
            float v = qb[(size_t)(k0 + r) * NPIX + c];
            v = fmaf(v, qs[k0 + r], qh[k0 + r]);
            q2s[r * 132 + c] = (v > 0.0f) ? v : 0.01f * v;
        }
        __syncthreads();
#pragma unroll
        for (int kk = 0; kk < 16; kk++) {
            float v = q2s[kk * 132 + nl];
#pragma unroll
            for (int j = 0; j < 10; j++) {
                if (j < nj) acc[j] = fmaf(v, k2s[(k0 + kk) * PTOK + p0 + j], acc[j]);
            }
        }
        __syncthreads();
    }
    for (int j = 0; j < nj; j++) L[(p0 + j) * 132 + nl] = acc[j];
    __syncthreads();
    float mx = -3.4e38f;
#pragma unroll
    for (int p = 0; p < PTOK; p++) mx = fmaxf(mx, L[p * 132 + nl]);
    float ssum = 0.0f;
    float er[10];
#pragma unroll
    for (int p = 0; p < PTOK; p++) {
        float e = expf(L[p * 132 + nl] - mx);
        ssum += e;
        int j = p - p0;
        if (j >= 0 && j < nj) er[j] = e;
    }
    float inv = 1.0f / ssum;
    for (int j = 0; j < nj; j++)
        g_sim2[((size_t)b * PTOK + p0 + j) * NPIX + n0 + nl] = er[j] * inv;
}

// ---------------- epilogue: out[b,o,n] = sum_p sim2[b,p,n] * M[b,o,p] + Wb[o] ----------------
__global__ __launch_bounds__(256) void kC2(const float* __restrict__ Wb, float* __restrict__ out) {
    __shared__ __align__(16) float Ms[COUT * 20];
    __shared__ float wbs[COUT];
    const int b = blockIdx.y;
    const int n = blockIdx.x * 256 + threadIdx.x;
    for (int i = threadIdx.x; i < COUT * 20; i += 256) Ms[i] = g_M[(size_t)b * COUT * 20 + i];
    for (int i = threadIdx.x; i < COUT; i += 256) wbs[i] = Wb[i];
    __syncthreads();
    float sr[PTOK];
#pragma unroll
    for (int p = 0; p < PTOK; p++) sr[p] = g_sim2[((size_t)b * PTOK + p) * NPIX + n];
    float* ob = out + (size_t)b * COUT * NPIX + n;
#pragma unroll 2
    for (int o = 0; o < COUT; o++) {
        const float4* mp = reinterpret_cast<const float4*>(&Ms[o * 20]);
        float4 a0 = mp[0], a1 = mp[1], a2 = mp[2], a3 = mp[3];
        float a = wbs[o];
        a = fmaf(a0.x, sr[0], a);  a = fmaf(a0.y, sr[1], a);
        a = fmaf(a0.z, sr[2], a);  a = fmaf(a0.w, sr[3], a);
        a = fmaf(a1.x, sr[4], a);  a = fmaf(a1.y, sr[5], a);
        a = fmaf(a1.z, sr[6], a);  a = fmaf(a1.w, sr[7], a);
        a = fmaf(a2.x, sr[8], a);  a = fmaf(a2.y, sr[9], a);
        a = fmaf(a2.z, sr[10], a); a = fmaf(a2.w, sr[11], a);
        a = fmaf(a3.x, sr[12], a); a = fmaf(a3.y, sr[13], a);
        a = fmaf(a3.z, sr[14], a); a = fmaf(a3.w, sr[15], a);
        a = fmaf(Ms[o * 20 + 16], sr[16], a);
        a = fmaf(Ms[o * 20 + 17], sr[17], a);
        a = fmaf(Ms[o * 20 + 18], sr[18], a);
        ob[(size_t)o * NPIX] = a;
    }
}

// ---------------- launcher ----------------
extern "C" void kernel_launch(void* const* d_in, const int* in_sizes, int n_in,
                              void* d_out, int out_size) {
    const float* x        = (const float*)d_in[0];
    const float* proxy    = (const float*)d_in[1];
    const float* fk_w     = (const float*)d_in[2];
    const float* fk_b     = (const float*)d_in[3];
    const float* fk_g     = (const float*)d_in[4];
    const float* fk_beta  = (const float*)d_in[5];
    const float* fq_w     = (const float*)d_in[6];
    const float* fq_b     = (const float*)d_in[7];
    const float* fq_g     = (const float*)d_in[8];
    const float* fq_beta  = (const float*)d_in[9];
    const float* fv_w     = (const float*)d_in[10];
    const float* fv_b     = (const float*)d_in[11];
    const float* pq_w     = (const float*)d_in[12];
    const float* pq_b     = (const float*)d_in[13];
    const float* pq_g     = (const float*)d_in[14];
    const float* pq_beta  = (const float*)d_in[15];
    const float* pk_w     = (const float*)d_in[16];
    const float* pk_b     = (const float*)d_in[17];
    const float* pk_g     = (const float*)d_in[18];
    const float* pk_beta  = (const float*)d_in[19];
    const float* W_w      = (const float*)d_in[20];
    const float* W_b      = (const float*)d_in[21];
    float* out = (float*)d_out;

    kInit<<<160, 256>>>();
    kA<<<dim3(128, 6, 8), 256>>>(x, fk_w, fk_b, fq_w, fq_b, fv_w, fv_b);
    kStats<<<dim3(512, 16), 256>>>();
    kFin<<<1, 512>>>(fk_g, fk_beta, fq_g, fq_beta);
    kT<<<1, 256>>>(proxy, pq_w, pq_b, pq_g, pq_beta, pk_g ? pk_w : pk_w, pk_b, pk_g, pk_beta);
    kB1<<<dim3(64, 8), 256>>>();
    kB2<<<dim3(PTOK, 8), 256>>>();
    kB3<<<dim3(8, 4, 8), 256>>>();
    kM<<<8, 256>>>(W_w);
    kC1<<<dim3(128, 8), 256>>>();
    kC2<<<dim3(64, 8), 256>>>(W_b, out);
}

// round 5
// speedup vs baseline: 1.3092x; 1.3092x over previous
#include <cuda_runtime.h>
#include <cuda_bf16.h>
#include <math.h>
#include <stdint.h>

#define BATCH 8
#define CIN   512
#define CK    256
#define CV    256
#define COUT  512
#define NPIX  16384
#define PTOK  19
#define BN_EPS 1e-5f

// ---------------- scratch (static device memory; no allocations) ----------------
__device__ __align__(16) float g_k1[BATCH * CK * NPIX];
__device__ __align__(16) float g_q2[BATCH * CK * NPIX];
__device__ __align__(16) float g_v1[BATCH * CV * NPIX];
__device__ __align__(16) float g_logits1[BATCH * PTOK * NPIX];
__device__ __align__(16) float g_sim2[BATCH * PTOK * NPIX];
__device__ __align__(16) float g_ctx[BATCH * PTOK * CV];
__device__ __align__(16) float g_M[BATCH * COUT * 20];
__device__ float g_q1[CK * PTOK];
__device__ float g_k2[CK * PTOK];
__device__ float g_stat[4 * CK];
__device__ float g_kscale[CK], g_kshift[CK], g_qscale[CK], g_qshift[CK];
// bf16 split weights only (tiny): rows fk(256) | fq(256) | fv(256)
__device__ __align__(16) __nv_bfloat16 g_wh[768 * CIN];
__device__ __align__(16) __nv_bfloat16 g_wl[768 * CIN];

// ---------------- init ----------------
__global__ void kInit() {
    int i = blockIdx.x * blockDim.x + threadIdx.x;
    if (i < 4 * CK) g_stat[i] = 0.0f;
    int j = i - 4 * CK;
    if (j >= 0 && j < BATCH * PTOK * CV) g_ctx[j] = 0.0f;
}

// ---------------- bf16 hi/lo split helpers ----------------
__device__ __forceinline__ void split1(float v, unsigned short& h, unsigned short& l) {
    __nv_bfloat16 hb = __float2bfloat16_rn(v);
    h = __bfloat16_as_ushort(hb);
    l = __bfloat16_as_ushort(__float2bfloat16_rn(v - __bfloat162float(hb)));
}

#define W_F4  (768 * CIN / 4)   // 98,304
#define W_BLK 48

// weights-only conversion (fk | fq | fv stacked)
__global__ __launch_bounds__(256) void kCvtW(
    const float* __restrict__ fkw, const float* __restrict__ fqw, const float* __restrict__ fvw)
{
#pragma unroll
    for (int i = 0; i < 8; i++) {
        size_t fi = (size_t)blockIdx.x * 2048 + threadIdx.x + i * 256;
        if (fi >= W_F4) continue;
        size_t e = fi * 4;
        int tensor = (int)(e >> 17);           // /131072
        size_t off = e & 131071;
        const float* src = (tensor == 0) ? fkw : (tensor == 1 ? fqw : fvw);
        float4 v = *(const float4*)&src[off];
        unsigned short h0, l0, h1, l1, h2, l2, h3, l3;
        split1(v.x, h0, l0); split1(v.y, h1, l1);
        split1(v.z, h2, l2); split1(v.w, h3, l3);
        uint2 h, l;
        h.x = (uint32_t)h0 | ((uint32_t)h1 << 16);
        h.y = (uint32_t)h2 | ((uint32_t)h3 << 16);
        l.x = (uint32_t)l0 | ((uint32_t)l1 << 16);
        l.y = (uint32_t)l2 | ((uint32_t)l3 << 16);
        ((uint2*)g_wh)[fi] = h;
        ((uint2*)g_wl)[fi] = l;
    }
}

// ---------------- Pass A: split-bf16 tensor-core GEMM ----------------
// y[m,n] = sum_c W[m,c] x[b,c,n] + bias[m], via Wh*Xh + Wh*Xl + Wl*Xh.
// X is read as fp32 and split in registers. CTA: 128m x 128n, K chunk 32,
// 8 warps (2m x 4n), warp tile 64m x 32n.
#define PITCH 17  // u32 words per 32-bf16 smem row (bank rotation)

#define MMA_B16(c, a, bf) asm volatile( \
    "mma.sync.aligned.m16n8k16.row.col.f32.bf16.bf16.f32 " \
    "{%0,%1,%2,%3},{%4,%5,%6,%7},{%8,%9},{%0,%1,%2,%3};" \
    : "+f"(c[0]), "+f"(c[1]), "+f"(c[2]), "+f"(c[3]) \
    : "r"(a[0]), "r"(a[1]), "r"(a[2]), "r"(a[3]), "r"(bf[0]), "r"(bf[1]))

__global__ __launch_bounds__(256) void kA2(
    const float* __restrict__ x,
    const float* __restrict__ fk_b, const float* __restrict__ fq_b, const float* __restrict__ fv_b)
{
    __shared__ uint32_t sAh[128 * PITCH], sAl[128 * PITCH];
    __shared__ uint32_t sBh[128 * PITCH], sBl[128 * PITCH];

    const int t = threadIdx.x;
    const int lane = t & 31, warp = t >> 5;
    const int wm = warp >> 2, wn = warp & 3;
    const int n0 = blockIdx.x * 128;
    const int by = blockIdx.y;
    const int b  = blockIdx.z;
    const int mbase = by * 128;

    const float* bptr; float* dst;
    if (by < 2)      { bptr = fk_b; dst = g_k1; }
    else if (by < 4) { bptr = fq_b; dst = g_q2; }
    else             { bptr = fv_b; dst = g_v1; }
    const int chbase = (by & 1) * 128;

    // fill mappings
    const int am = t >> 1;                 // A row 0..127
    const int ak = (t & 1) * 16;           // A k sub-offset
    const __nv_bfloat16* gAh = g_wh + (size_t)(mbase + am) * CIN;
    const __nv_bfloat16* gAl = g_wl + (size_t)(mbase + am) * CIN;
    const int bj = t & 15;                 // B n-block (8 wide)
    const int bk = (t >> 4) * 2;           // B k-pair
    const float* gX = x + ((size_t)b * CIN) * NPIX + n0 + bj * 8;

    float acc[4][4][4];
#pragma unroll
    for (int i = 0; i < 4; i++)
#pragma unroll
        for (int j = 0; j < 4; j++)
#pragma unroll
            for (int r = 0; r < 4; r++) acc[i][j][r] = 0.0f;

    uint4 rAh0, rAh1, rAl0, rAl1;
    float4 rx00, rx01, rx10, rx11;

#define LOADC(k0) do { \
    rAh0 = *(const uint4*)(gAh + (k0) + ak); \
    rAh1 = *(const uint4*)(gAh + (k0) + ak + 8); \
    rAl0 = *(const uint4*)(gAl + (k0) + ak); \
    rAl1 = *(const uint4*)(gAl + (k0) + ak + 8); \
    rx00 = *(const float4*)(gX + (size_t)((k0) + bk) * NPIX); \
    rx01 = *(const float4*)(gX + (size_t)((k0) + bk) * NPIX + 4); \
    rx10 = *(const float4*)(gX + (size_t)((k0) + bk + 1) * NPIX); \
    rx11 = *(const float4*)(gX + (size_t)((k0) + bk + 1) * NPIX + 4); \
} while (0)

#define STOREC() do { \
    int wofs = am * PITCH + (ak >> 1); \
    const uint32_t* pa0 = (const uint32_t*)&rAh0; const uint32_t* pa1 = (const uint32_t*)&rAh1; \
    const uint32_t* pb0 = (const uint32_t*)&rAl0; const uint32_t* pb1 = (const uint32_t*)&rAl1; \
    _Pragma("unroll") for (int i = 0; i < 4; i++) { \
        sAh[wofs + i] = pa0[i]; sAh[wofs + 4 + i] = pa1[i]; \
        sAl[wofs + i] = pb0[i]; sAl[wofs + 4 + i] = pb1[i]; } \
    float bv0[8] = {rx00.x, rx00.y, rx00.z, rx00.w, rx01.x, rx01.y, rx01.z, rx01.w}; \
    float bv1[8] = {rx10.x, rx10.y, rx10.z, rx10.w, rx11.x, rx11.y, rx11.z, rx11.w}; \
    _Pragma("unroll") for (int i = 0; i < 8; i++) { \
        unsigned short h0, l0, h1, l1; \
        split1(bv0[i], h0, l0); split1(bv1[i], h1, l1); \
        sBh[(bj * 8 + i) * PITCH + (bk >> 1)] = (uint32_t)h0 | ((uint32_t)h1 << 16); \
        sBl[(bj * 8 + i) * PITCH + (bk >> 1)] = (uint32_t)l0 | ((uint32_t)l1 << 16); } \
} while (0)

    LOADC(0);
    STOREC();

    for (int c = 0; c < 16; c++) {
        __syncthreads();
        if (c < 15) LOADC((c + 1) * 32);
        // compute 2 k16-steps from smem
#pragma unroll
        for (int s = 0; s < 2; s++) {
            uint32_t a_h[4][4], a_l[4][4], b_h[4][2], b_l[4][2];
            const int aw = s * 8 + (lane & 3);
#pragma unroll
            for (int mf = 0; mf < 4; mf++) {
                int r = wm * 64 + mf * 16 + (lane >> 2);
                a_h[mf][0] = sAh[r * PITCH + aw];
                a_h[mf][1] = sAh[(r + 8) * PITCH + aw];
                a_h[mf][2] = sAh[r * PITCH + aw + 4];
                a_h[mf][3] = sAh[(r + 8) * PITCH + aw + 4];
                a_l[mf][0] = sAl[r * PITCH + aw];
                a_l[mf][1] = sAl[(r + 8) * PITCH + aw];
                a_l[mf][2] = sAl[r * PITCH + aw + 4];
                a_l[mf][3] = sAl[(r + 8) * PITCH + aw + 4];
            }
#pragma unroll
            for (int nf = 0; nf < 4; nf++) {
                int col = wn * 32 + nf * 8 + (lane >> 2);
                b_h[nf][0] = sBh[col * PITCH + aw];
                b_h[nf][1] = sBh[col * PITCH + aw + 4];
                b_l[nf][0] = sBl[col * PITCH + aw];
                b_l[nf][1] = sBl[col * PITCH + aw + 4];
            }
#pragma unroll
            for (int mf = 0; mf < 4; mf++)
#pragma unroll
                for (int nf = 0; nf < 4; nf++) {
                    MMA_B16(acc[mf][nf], a_h[mf], b_h[nf]);
                    MMA_B16(acc[mf][nf], a_h[mf], b_l[nf]);
                    MMA_B16(acc[mf][nf], a_l[mf], b_h[nf]);
                }
        }
        __syncthreads();
        if (c < 15) STOREC();
    }

    // epilogue: add bias, write fp32
    const size_t obase = (size_t)b * CK * NPIX;
#pragma unroll
    for (int mf = 0; mf < 4; mf++) {
        int r0 = chbase + wm * 64 + mf * 16 + (lane >> 2);
        float bias0 = bptr[r0], bias1 = bptr[r0 + 8];
#pragma unroll
        for (int nf = 0; nf < 4; nf++) {
            int n = n0 + wn * 32 + nf * 8 + (lane & 3) * 2;
            float2 v0 = make_float2(acc[mf][nf][0] + bias0, acc[mf][nf][1] + bias0);
            float2 v1 = make_float2(acc[mf][nf][2] + bias1, acc[mf][nf][3] + bias1);
            *(float2*)&dst[obase + (size_t)r0 * NPIX + n] = v0;
            *(float2*)&dst[obase + (size_t)(r0 + 8) * NPIX + n] = v1;
        }
    }
}

// ---------------- BN stats ----------------
__global__ __launch_bounds__(256) void kStats() {
    const int ch = blockIdx.x;
    const int chunk = blockIdx.y;
    const float* src = (ch < CK) ? g_k1 : g_q2;
    const int c = ch & (CK - 1);
    const int b = chunk >> 1;
    const int nh = (chunk & 1) * (NPIX / 2);
    const float* base = src + ((size_t)b * CK + c) * NPIX + nh;
    float sum = 0.0f, sq = 0.0f;
    for (int i = threadIdx.x; i < NPIX / 2; i += 256) {
        float v = base[i];
        sum += v; sq += v * v;
    }
    __shared__ float s1[256], s2[256];
    s1[threadIdx.x] = sum; s2[threadIdx.x] = sq;
    __syncthreads();
    for (int off = 128; off > 0; off >>= 1) {
        if (threadIdx.x < off) {
            s1[threadIdx.x] += s1[threadIdx.x + off];
            s2[threadIdx.x] += s2[threadIdx.x + off];
        }
        __syncthreads();
    }
    if (threadIdx.x == 0) {
        int b2 = (ch < CK) ? 0 : 2 * CK;
        atomicAdd(&g_stat[b2 + c], s1[0]);
        atomicAdd(&g_stat[b2 + CK + c], s2[0]);
    }
}

// ---------------- finalize BN scale/shift ----------------
__global__ void kFin(const float* __restrict__ fk_g, const float* __restrict__ fk_beta,
                     const float* __restrict__ fq_g, const float* __restrict__ fq_beta) {
    int t = threadIdx.x;
    const float inv = 1.0f / (float)(BATCH * NPIX);
    if (t < CK) {
        float mean = g_stat[t] * inv;
        float var = g_stat[CK + t] * inv - mean * mean;
        float sc = fk_g[t] * rsqrtf(var + BN_EPS);
        g_kscale[t] = sc;
        g_kshift[t] = fk_beta[t] - mean * sc;
    } else if (t < 2 * CK) {
        int c = t - CK;
        float mean = g_stat[2 * CK + c] * inv;
        float var = g_stat[3 * CK + c] * inv - mean * mean;
        float sc = fq_g[c] * rsqrtf(var + BN_EPS);
        g_qscale[c] = sc;
        g_qshift[c] = fq_beta[c] - mean * sc;
    }
}

// ---------------- tiny proxy-side projections ----------------
__global__ __launch_bounds__(256) void kT(
    const float* __restrict__ proxy,
    const float* __restrict__ pq_w, const float* __restrict__ pq_b,
    const float* __restrict__ pq_g, const float* __restrict__ pq_beta,
    const float* __restrict__ pk_w, const float* __restrict__ pk_b,
    const float* __restrict__ pk_g, const float* __restrict__ pk_beta)
{
    __shared__ float sp[CIN * PTOK];
    for (int i = threadIdx.x; i < CIN * PTOK; i += 256) sp[i] = proxy[i];
    __syncthreads();
    const int k = threadIdx.x;
    for (int which = 0; which < 2; which++) {
        const float* w  = which ? pk_w : pq_w;
        const float* bb = which ? pk_b : pq_b;
        const float* g  = which ? pk_g : pq_g;
        const float* be = which ? pk_beta : pq_beta;
        float* dstp = which ? g_k2 : g_q1;
        float acc[PTOK];
#pragma unroll
        for (int p = 0; p < PTOK; p++) acc[p] = bb[k];
        for (int c = 0; c < CIN; c++) {
            float wv = w[(size_t)k * CIN + c];
#pragma unroll
            for (int p = 0; p < PTOK; p++) acc[p] = fmaf(wv, sp[c * PTOK + p], acc[p]);
        }
        float mean = 0.0f;
#pragma unroll
        for (int p = 0; p < PTOK; p++) mean += acc[p];
        mean *= (1.0f / PTOK);
        float var = 0.0f;
#pragma unroll
        for (int p = 0; p < PTOK; p++) { float d = acc[p] - mean; var += d * d; }
        var *= (1.0f / PTOK);
        float sc = g[k] * rsqrtf(var + BN_EPS);
        float sh = be[k] - mean * sc;
#pragma unroll
        for (int p = 0; p < PTOK; p++) {
            float z = acc[p] * sc + sh;
            dstp[k * PTOK + p] = (z > 0.0f) ? z : 0.01f * z;
        }
    }
}

// ---------------- stage 1 logits ----------------
__global__ __launch_bounds__(256) void kB1() {
    __shared__ float q1s[CK * PTOK];
    __shared__ float ks[CK], kh[CK];
    const int b = blockIdx.y;
    const int n = blockIdx.x * 256 + threadIdx.x;
    for (int i = threadIdx.x; i < CK * PTOK; i += 256) q1s[i] = g_q1[i];
    if (threadIdx.x < CK) { ks[threadIdx.x] = g_kscale[threadIdx.x]; kh[threadIdx.x] = g_kshift[threadIdx.x]; }
    __syncthreads();
    float acc[PTOK];
#pragma unroll
    for (int p = 0; p < PTOK; p++) acc[p] = 0.0f;
    const float* kp = g_k1 + (size_t)b * CK * NPIX + n;
    for (int k = 0; k < CK; k++) {
        float v = kp[(size_t)k * NPIX];
        v = fmaf(v, ks[k], kh[k]);
        v = (v > 0.0f) ? v : 0.01f * v;
#pragma unroll
        for (int p = 0; p < PTOK; p++) acc[p] = fmaf(q1s[k * PTOK + p], v, acc[p]);
    }
    float* out = g_logits1 + (size_t)b * PTOK * NPIX + n;
#pragma unroll
    for (int p = 0; p < PTOK; p++) out[(size_t)p * NPIX] = acc[p];
}

// ---------------- stage 1 softmax over N ----------------
__global__ __launch_bounds__(256) void kB2() {
    const int p = blockIdx.x, b = blockIdx.y;
    float* row = g_logits1 + ((size_t)b * PTOK + p) * NPIX;
    __shared__ float red[256];
    const int tid = threadIdx.x;
    float m = -3.4e38f;
    for (int i = tid; i < NPIX; i += 256) m = fmaxf(m, row[i]);
    red[tid] = m; __syncthreads();
    for (int off = 128; off > 0; off >>= 1) {
        if (tid < off) red[tid] = fmaxf(red[tid], red[tid + off]);
        __syncthreads();
    }
    float mx = red[0];
    __syncthreads();
    float s = 0.0f;
    for (int i = tid; i < NPIX; i += 256) s += expf(row[i] - mx);
    red[tid] = s; __syncthreads();
    for (int off = 128; off > 0; off >>= 1) {
        if (tid < off) red[tid] += red[tid + off];
        __syncthreads();
    }
    float inv = 1.0f / red[0];
    for (int i = tid; i < NPIX; i += 256) row[i] = expf(row[i] - mx) * inv;
}

// ---------------- stage 1 context ----------------
__global__ __launch_bounds__(256) void kB3() {
    __shared__ float vs[64 * 129];
    __shared__ float ss[PTOK * 129];
    const int nch = blockIdx.x;
    const int vt  = blockIdx.y;
    const int b   = blockIdx.z;
    const int v0 = vt * 64;
    const int tid = threadIdx.x;
    const int tx16 = tid & 15;
    const int ty   = (tid >> 4) & 3;
    const int tz   = tid >> 6;
    float acc[4][5];
#pragma unroll
    for (int i = 0; i < 4; i++)
#pragma unroll
        for (int j = 0; j < 5; j++) acc[i][j] = 0.0f;

    const float* vbase = g_v1 + ((size_t)b * CV + v0) * NPIX;
    const float* sbase = g_logits1 + (size_t)b * PTOK * NPIX;

    for (int st = 0; st < 16; st++) {
        const int nb = nch * 2048 + st * 128;
        for (int s = tid; s < 64 * 128; s += 256) {
            int r = s >> 7, c = s & 127;
            vs[r * 129 + c] = vbase[(size_t)r * NPIX + nb + c];
        }
        for (int s = tid; s < PTOK * 128; s += 256) {
            int r = s >> 7, c = s & 127;
            ss[r * 129 + c] = sbase[(size_t)r * NPIX + nb + c];
        }
        __syncthreads();
#pragma unroll 4
        for (int nn = tz * 32; nn < tz * 32 + 32; nn++) {
            float sv[5];
#pragma unroll
            for (int j = 0; j < 5; j++) {
                int p = ty * 5 + j;
                sv[j] = (p < PTOK) ? ss[p * 129 + nn] : 0.0f;
            }
#pragma unroll
            for (int i = 0; i < 4; i++) {
                float vv = vs[(tx16 * 4 + i) * 129 + nn];
#pragma unroll
                for (int j = 0; j < 5; j++) acc[i][j] = fmaf(vv, sv[j], acc[i][j]);
            }
        }
        __syncthreads();
    }
#pragma unroll
    for (int j = 0; j < 5; j++) {
        int p = ty * 5 + j;
        if (p < PTOK) {
#pragma unroll
            for (int i = 0; i < 4; i++)
                atomicAdd(&g_ctx[((size_t)b * PTOK + p) * CV + v0 + tx16 * 4 + i], acc[i][j]);
        }
    }
}

// ---------------- M precompute ----------------
__global__ __launch_bounds__(256) void kM(const float* __restrict__ Ww) {
    __shared__ float ctxs[PTOK * CV];
    const int b = blockIdx.x;
    for (int i = threadIdx.x; i < PTOK * CV; i += 256)
        ctxs[i] = g_ctx[(size_t)b * PTOK * CV + i];
    __syncthreads();
    for (int rep = 0; rep < 2; rep++) {
        int o = rep * 256 + threadIdx.x;
        float acc[PTOK];
#pragma unroll
        for (int p = 0; p < PTOK; p++) acc[p] = 0.0f;
        for (int v = 0; v < CV; v++) {
            float w = Ww[(size_t)o * CV + v];
#pragma unroll
            for (int p = 0; p < PTOK; p++) acc[p] = fmaf(w, ctxs[p * CV + v], acc[p]);
        }
        float* dstp = &g_M[((size_t)b * COUT + o) * 20];
#pragma unroll
        for (int p = 0; p < PTOK; p++) dstp[p] = acc[p];
        dstp[19] = 0.0f;
    }
}

// ---------------- stage 2: logits + softmax over P ----------------
__global__ __launch_bounds__(256) void kC1() {
    __shared__ float k2s[CK * PTOK];
    __shared__ float q2s[16 * 132];
    __shared__ float L[PTOK * 132];
    __shared__ float qs[CK], qh[CK];
    const int b = blockIdx.y;
    const int n0 = blockIdx.x * 128;
    const int tid = threadIdx.x;
    const int nl = tid & 127;
    const int half = tid >> 7;
    for (int i = tid; i < CK * PTOK; i += 256) k2s[i] = g_k2[i];
    if (tid < CK) { qs[tid] = g_qscale[tid]; qh[tid] = g_qshift[tid]; }
    __syncthreads();
    const int p0 = half * 10;
    const int nj = half ? 9 : 10;
    float acc[10];
#pragma unroll
    for (int j = 0; j < 10; j++) acc[j] = 0.0f;
    const float* qb = g_q2 + (size_t)b * CK * NPIX + n0;
    for (int k0 = 0; k0 < CK; k0 += 16) {
        for (int s = tid; s < 16 * 128; s += 256) {
            int r = s >> 7, c = s & 127;
            float v = qb[(size_t)(k0 + r) * NPIX + c];
            v = fmaf(v, qs[k0 + r], qh[k0 + r]);
            q2s[r * 132 + c] = (v > 0.0f) ? v : 0.01f * v;
        }
        __syncthreads();
#pragma unroll
        for (int kk = 0; kk < 16; kk++) {
            float v = q2s[kk * 132 + nl];
#pragma unroll
            for (int j = 0; j < 10; j++) {
                if (j < nj) acc[j] = fmaf(v, k2s[(k0 + kk) * PTOK + p0 + j], acc[j]);
            }
        }
        __syncthreads();
    }
    for (int j = 0; j < nj; j++) L[(p0 + j) * 132 + nl] = acc[j];
    __syncthreads();
    float mx = -3.4e38f;
#pragma unroll
    for (int p = 0; p < PTOK; p++) mx = fmaxf(mx, L[p * 132 + nl]);
    float ssum = 0.0f;
    float er[10];
#pragma unroll
    for (int p = 0; p < PTOK; p++) {
        float e = expf(L[p * 132 + nl] - mx);
        ssum += e;
        int j = p - p0;
        if (j >= 0 && j < nj) er[j] = e;
    }
    float inv = 1.0f / ssum;
    for (int j = 0; j < nj; j++)
        g_sim2[((size_t)b * PTOK + p0 + j) * NPIX + n0 + nl] = er[j] * inv;
}

// ---------------- epilogue ----------------
__global__ __launch_bounds__(256) void kC2(const float* __restrict__ Wb, float* __restrict__ out) {
    __shared__ __align__(16) float Ms[COUT * 20];
    __shared__ float wbs[COUT];
    const int b = blockIdx.y;
    const int n = blockIdx.x * 256 + threadIdx.x;
    for (int i = threadIdx.x; i < COUT * 20; i += 256) Ms[i] = g_M[(size_t)b * COUT * 20 + i];
    for (int i = threadIdx.x; i < COUT; i += 256) wbs[i] = Wb[i];
    __syncthreads();
    float sr[PTOK];
#pragma unroll
    for (int p = 0; p < PTOK; p++) sr[p] = g_sim2[((size_t)b * PTOK + p) * NPIX + n];
    float* ob = out + (size_t)b * COUT * NPIX + n;
#pragma unroll 2
    for (int o = 0; o < COUT; o++) {
        const float4* mp = reinterpret_cast<const float4*>(&Ms[o * 20]);
        float4 a0 = mp[0], a1 = mp[1], a2 = mp[2], a3 = mp[3];
        float a = wbs[o];
        a = fmaf(a0.x, sr[0], a);  a = fmaf(a0.y, sr[1], a);
        a = fmaf(a0.z, sr[2], a);  a = fmaf(a0.w, sr[3], a);
        a = fmaf(a1.x, sr[4], a);  a = fmaf(a1.y, sr[5], a);
        a = fmaf(a1.z, sr[6], a);  a = fmaf(a1.w, sr[7], a);
        a = fmaf(a2.x, sr[8], a);  a = fmaf(a2.y, sr[9], a);
        a = fmaf(a2.z, sr[10], a); a = fmaf(a2.w, sr[11], a);
        a = fmaf(a3.x, sr[12], a); a = fmaf(a3.y, sr[13], a);
        a = fmaf(a3.z, sr[14], a); a = fmaf(a3.w, sr[15], a);
        a = fmaf(Ms[o * 20 + 16], sr[16], a);
        a = fmaf(Ms[o * 20 + 17], sr[17], a);
        a = fmaf(Ms[o * 20 + 18], sr[18], a);
        ob[(size_t)o * NPIX] = a;
    }
}

// ---------------- launcher ----------------
extern "C" void kernel_launch(void* const* d_in, const int* in_sizes, int n_in,
                              void* d_out, int out_size) {
    const float* x        = (const float*)d_in[0];
    const float* proxy    = (const float*)d_in[1];
    const float* fk_w     = (const float*)d_in[2];
    const float* fk_b     = (const float*)d_in[3];
    const float* fk_g     = (const float*)d_in[4];
    const float* fk_beta  = (const float*)d_in[5];
    const float* fq_w     = (const float*)d_in[6];
    const float* fq_b     = (const float*)d_in[7];
    const float* fq_g     = (const float*)d_in[8];
    const float* fq_beta  = (const float*)d_in[9];
    const float* fv_w     = (const float*)d_in[10];
    const float* fv_b     = (const float*)d_in[11];
    const float* pq_w     = (const float*)d_in[12];
    const float* pq_b     = (const float*)d_in[13];
    const float* pq_g     = (const float*)d_in[14];
    const float* pq_beta  = (const float*)d_in[15];
    const float* pk_w     = (const float*)d_in[16];
    const float* pk_b     = (const float*)d_in[17];
    const float* pk_g     = (const float*)d_in[18];
    const float* pk_beta  = (const float*)d_in[19];
    const float* W_w      = (const float*)d_in[20];
    const float* W_b      = (const float*)d_in[21];
    float* out = (float*)d_out;

    kInit<<<160, 256>>>();
    kCvtW<<<W_BLK, 256>>>(fk_w, fq_w, fv_w);
    kA2<<<dim3(128, 6, 8), 256>>>(x, fk_b, fq_b, fv_b);
    kStats<<<dim3(512, 16), 256>>>();
    kFin<<<1, 512>>>(fk_g, fk_beta, fq_g, fq_beta);
    kT<<<1, 256>>>(proxy, pq_w, pq_b, pq_g, pq_beta, pk_w, pk_b, pk_g, pk_beta);
    kB1<<<dim3(64, 8), 256>>>();
    kB2<<<dim3(PTOK, 8), 256>>>();
    kB3<<<dim3(8, 4, 8), 256>>>();
    kM<<<8, 256>>>(W_w);
    kC1<<<dim3(128, 8), 256>>>();
    kC2<<<dim3(64, 8), 256>>>(W_b, out);
}

// round 6
// speedup vs baseline: 1.4637x; 1.1180x over previous
#include <cuda_runtime.h>
#include <cuda_bf16.h>
#include <math.h>
#include <stdint.h>

#define BATCH 8
#define CIN   512
#define CK    256
#define CV    256
#define COUT  512
#define NPIX  16384
#define PTOK  19
#define BN_EPS 1e-5f

// ---------------- scratch (static device memory; no allocations) ----------------
__device__ __align__(16) float g_k1[BATCH * CK * NPIX];
__device__ __align__(16) float g_q2[BATCH * CK * NPIX];
__device__ __align__(16) float g_logits1[BATCH * PTOK * NPIX];
__device__ __align__(16) float g_sim2[BATCH * PTOK * NPIX];
__device__ __align__(16) float g_y[BATCH * PTOK * CIN];      // y[b,p,c] = sum_n sim1*x
__device__ __align__(16) float g_ctx[BATCH * PTOK * CV];
__device__ __align__(16) float g_M[BATCH * COUT * 20];
__device__ float g_q1[CK * PTOK];
__device__ float g_k2[CK * PTOK];
__device__ float g_stat[4 * CK];
__device__ float g_kscale[CK], g_kshift[CK], g_qscale[CK], g_qshift[CK];
// bf16 split weights (fk 256 rows | fq 256 rows)
__device__ __align__(16) __nv_bfloat16 g_wh[512 * CIN];
__device__ __align__(16) __nv_bfloat16 g_wl[512 * CIN];

// ---------------- init: zero atomically-accumulated buffers ----------------
__global__ void kInit() {
    int i = blockIdx.x * blockDim.x + threadIdx.x;
    if (i < 4 * CK) g_stat[i] = 0.0f;
    int j = i - 4 * CK;
    if (j >= 0 && j < BATCH * PTOK * CIN) g_y[j] = 0.0f;
}

// ---------------- bf16 hi/lo split helpers ----------------
__device__ __forceinline__ void split1(float v, unsigned short& h, unsigned short& l) {
    __nv_bfloat16 hb = __float2bfloat16_rn(v);
    h = __bfloat16_as_ushort(hb);
    l = __bfloat16_as_ushort(__float2bfloat16_rn(v - __bfloat162float(hb)));
}

#define W_F4  (512 * CIN / 4)   // 65,536
#define W_BLK 32

// weights-only conversion (fk | fq stacked)
__global__ __launch_bounds__(256) void kCvtW(
    const float* __restrict__ fkw, const float* __restrict__ fqw)
{
#pragma unroll
    for (int i = 0; i < 8; i++) {
        size_t fi = (size_t)blockIdx.x * 2048 + threadIdx.x + i * 256;
        if (fi >= W_F4) continue;
        size_t e = fi * 4;
        const float* src = (e < 131072) ? fkw : fqw;
        size_t off = e & 131071;
        float4 v = *(const float4*)&src[off];
        unsigned short h0, l0, h1, l1, h2, l2, h3, l3;
        split1(v.x, h0, l0); split1(v.y, h1, l1);
        split1(v.z, h2, l2); split1(v.w, h3, l3);
        uint2 h, l;
        h.x = (uint32_t)h0 | ((uint32_t)h1 << 16);
        h.y = (uint32_t)h2 | ((uint32_t)h3 << 16);
        l.x = (uint32_t)l0 | ((uint32_t)l1 << 16);
        l.y = (uint32_t)l2 | ((uint32_t)l3 << 16);
        ((uint2*)g_wh)[fi] = h;
        ((uint2*)g_wl)[fi] = l;
    }
}

// ---------------- Pass A: split-bf16 tensor-core GEMM (fk + fq only) ----------------
// y[m,n] = sum_c W[m,c] x[b,c,n] + bias[m], via Wh*Xh + Wh*Xl + Wl*Xh.
// X read as fp32, split in registers. CTA: 128m x 128n, K chunk 32,
// 8 warps (2m x 4n), warp tile 64m x 32n.
#define PITCH 17  // u32 words per 32-bf16 smem row (bank rotation)

#define MMA_B16(c, a, bf) asm volatile( \
    "mma.sync.aligned.m16n8k16.row.col.f32.bf16.bf16.f32 " \
    "{%0,%1,%2,%3},{%4,%5,%6,%7},{%8,%9},{%0,%1,%2,%3};" \
    : "+f"(c[0]), "+f"(c[1]), "+f"(c[2]), "+f"(c[3]) \
    : "r"(a[0]), "r"(a[1]), "r"(a[2]), "r"(a[3]), "r"(bf[0]), "r"(bf[1]))

__global__ __launch_bounds__(256) void kA2(
    const float* __restrict__ x,
    const float* __restrict__ fk_b, const float* __restrict__ fq_b)
{
    __shared__ uint32_t sAh[128 * PITCH], sAl[128 * PITCH];
    __shared__ uint32_t sBh[128 * PITCH], sBl[128 * PITCH];

    const int t = threadIdx.x;
    const int lane = t & 31, warp = t >> 5;
    const int wm = warp >> 2, wn = warp & 3;
    const int n0 = blockIdx.x * 128;
    const int by = blockIdx.y;       // 0..3: fk0 fk1 fq0 fq1
    const int b  = blockIdx.z;
    const int mbase = by * 128;

    const float* bptr; float* dst;
    if (by < 2) { bptr = fk_b; dst = g_k1; }
    else        { bptr = fq_b; dst = g_q2; }
    const int chbase = (by & 1) * 128;

    const int am = t >> 1;                 // A row 0..127
    const int ak = (t & 1) * 16;           // A k sub-offset
    const __nv_bfloat16* gAh = g_wh + (size_t)(mbase + am) * CIN;
    const __nv_bfloat16* gAl = g_wl + (size_t)(mbase + am) * CIN;
    const int bj = t & 15;                 // B n-block (8 wide)
    const int bk = (t >> 4) * 2;           // B k-pair
    const float* gX = x + ((size_t)b * CIN) * NPIX + n0 + bj * 8;

    float acc[4][4][4];
#pragma unroll
    for (int i = 0; i < 4; i++)
#pragma unroll
        for (int j = 0; j < 4; j++)
#pragma unroll
            for (int r = 0; r < 4; r++) acc[i][j][r] = 0.0f;

    uint4 rAh0, rAh1, rAl0, rAl1;
    float4 rx00, rx01, rx10, rx11;

#define LOADC(k0) do { \
    rAh0 = *(const uint4*)(gAh + (k0) + ak); \
    rAh1 = *(const uint4*)(gAh + (k0) + ak + 8); \
    rAl0 = *(const uint4*)(gAl + (k0) + ak); \
    rAl1 = *(const uint4*)(gAl + (k0) + ak + 8); \
    rx00 = *(const float4*)(gX + (size_t)((k0) + bk) * NPIX); \
    rx01 = *(const float4*)(gX + (size_t)((k0) + bk) * NPIX + 4); \
    rx10 = *(const float4*)(gX + (size_t)((k0) + bk + 1) * NPIX); \
    rx11 = *(const float4*)(gX + (size_t)((k0) + bk + 1) * NPIX + 4); \
} while (0)

#define STOREC() do { \
    int wofs = am * PITCH + (ak >> 1); \
    const uint32_t* pa0 = (const uint32_t*)&rAh0; const uint32_t* pa1 = (const uint32_t*)&rAh1; \
    const uint32_t* pb0 = (const uint32_t*)&rAl0; const uint32_t* pb1 = (const uint32_t*)&rAl1; \
    _Pragma("unroll") for (int i = 0; i < 4; i++) { \
        sAh[wofs + i] = pa0[i]; sAh[wofs + 4 + i] = pa1[i]; \
        sAl[wofs + i] = pb0[i]; sAl[wofs + 4 + i] = pb1[i]; } \
    float bv0[8] = {rx00.x, rx00.y, rx00.z, rx00.w, rx01.x, rx01.y, rx01.z, rx01.w}; \
    float bv1[8] = {rx10.x, rx10.y, rx10.z, rx10.w, rx11.x, rx11.y, rx11.z, rx11.w}; \
    _Pragma("unroll") for (int i = 0; i < 8; i++) { \
        unsigned short h0, l0, h1, l1; \
        split1(bv0[i], h0, l0); split1(bv1[i], h1, l1); \
        sBh[(bj * 8 + i) * PITCH + (bk >> 1)] = (uint32_t)h0 | ((uint32_t)h1 << 16); \
        sBl[(bj * 8 + i) * PITCH + (bk >> 1)] = (uint32_t)l0 | ((uint32_t)l1 << 16); } \
} while (0)

    LOADC(0);
    STOREC();

    for (int c = 0; c < 16; c++) {
        __syncthreads();
        if (c < 15) LOADC((c + 1) * 32);
#pragma unroll
        for (int s = 0; s < 2; s++) {
            uint32_t a_h[4][4], a_l[4][4], b_h[4][2], b_l[4][2];
            const int aw = s * 8 + (lane & 3);
#pragma unroll
            for (int mf = 0; mf < 4; mf++) {
                int r = wm * 64 + mf * 16 + (lane >> 2);
                a_h[mf][0] = sAh[r * PITCH + aw];
                a_h[mf][1] = sAh[(r + 8) * PITCH + aw];
                a_h[mf][2] = sAh[r * PITCH + aw + 4];
                a_h[mf][3] = sAh[(r + 8) * PITCH + aw + 4];
                a_l[mf][0] = sAl[r * PITCH + aw];
                a_l[mf][1] = sAl[(r + 8) * PITCH + aw];
                a_l[mf][2] = sAl[r * PITCH + aw + 4];
                a_l[mf][3] = sAl[(r + 8) * PITCH + aw + 4];
            }
#pragma unroll
            for (int nf = 0; nf < 4; nf++) {
                int col = wn * 32 + nf * 8 + (lane >> 2);
                b_h[nf][0] = sBh[col * PITCH + aw];
                b_h[nf][1] = sBh[col * PITCH + aw + 4];
                b_l[nf][0] = sBl[col * PITCH + aw];
                b_l[nf][1] = sBl[col * PITCH + aw + 4];
            }
#pragma unroll
            for (int mf = 0; mf < 4; mf++)
#pragma unroll
                for (int nf = 0; nf < 4; nf++) {
                    MMA_B16(acc[mf][nf], a_h[mf], b_h[nf]);
                    MMA_B16(acc[mf][nf], a_h[mf], b_l[nf]);
                    MMA_B16(acc[mf][nf], a_l[mf], b_h[nf]);
                }
        }
        __syncthreads();
        if (c < 15) STOREC();
    }

    const size_t obase = (size_t)b * CK * NPIX;
#pragma unroll
    for (int mf = 0; mf < 4; mf++) {
        int r0 = chbase + wm * 64 + mf * 16 + (lane >> 2);
        float bias0 = bptr[r0], bias1 = bptr[r0 + 8];
#pragma unroll
        for (int nf = 0; nf < 4; nf++) {
            int n = n0 + wn * 32 + nf * 8 + (lane & 3) * 2;
            float2 v0 = make_float2(acc[mf][nf][0] + bias0, acc[mf][nf][1] + bias0);
            float2 v1 = make_float2(acc[mf][nf][2] + bias1, acc[mf][nf][3] + bias1);
            *(float2*)&dst[obase + (size_t)r0 * NPIX + n] = v0;
            *(float2*)&dst[obase + (size_t)(r0 + 8) * NPIX + n] = v1;
        }
    }
}

// ---------------- BN stats ----------------
__global__ __launch_bounds__(256) void kStats() {
    const int ch = blockIdx.x;
    const int chunk = blockIdx.y;
    const float* src = (ch < CK) ? g_k1 : g_q2;
    const int c = ch & (CK - 1);
    const int b = chunk >> 1;
    const int nh = (chunk & 1) * (NPIX / 2);
    const float* base = src + ((size_t)b * CK + c) * NPIX + nh;
    float sum = 0.0f, sq = 0.0f;
    for (int i = threadIdx.x; i < NPIX / 2; i += 256) {
        float v = base[i];
        sum += v; sq += v * v;
    }
    __shared__ float s1[256], s2[256];
    s1[threadIdx.x] = sum; s2[threadIdx.x] = sq;
    __syncthreads();
    for (int off = 128; off > 0; off >>= 1) {
        if (threadIdx.x < off) {
            s1[threadIdx.x] += s1[threadIdx.x + off];
            s2[threadIdx.x] += s2[threadIdx.x + off];
        }
        __syncthreads();
    }
    if (threadIdx.x == 0) {
        int b2 = (ch < CK) ? 0 : 2 * CK;
        atomicAdd(&g_stat[b2 + c], s1[0]);
        atomicAdd(&g_stat[b2 + CK + c], s2[0]);
    }
}

// ---------------- finalize BN scale/shift ----------------
__global__ void kFin(const float* __restrict__ fk_g, const float* __restrict__ fk_beta,
                     const float* __restrict__ fq_g, const float* __restrict__ fq_beta) {
    int t = threadIdx.x;
    const float inv = 1.0f / (float)(BATCH * NPIX);
    if (t < CK) {
        float mean = g_stat[t] * inv;
        float var = g_stat[CK + t] * inv - mean * mean;
        float sc = fk_g[t] * rsqrtf(var + BN_EPS);
        g_kscale[t] = sc;
        g_kshift[t] = fk_beta[t] - mean * sc;
    } else if (t < 2 * CK) {
        int c = t - CK;
        float mean = g_stat[2 * CK + c] * inv;
        float var = g_stat[3 * CK + c] * inv - mean * mean;
        float sc = fq_g[c] * rsqrtf(var + BN_EPS);
        g_qscale[c] = sc;
        g_qshift[c] = fq_beta[c] - mean * sc;
    }
}

// ---------------- tiny proxy-side projections ----------------
__global__ __launch_bounds__(256) void kT(
    const float* __restrict__ proxy,
    const float* __restrict__ pq_w, const float* __restrict__ pq_b,
    const float* __restrict__ pq_g, const float* __restrict__ pq_beta,
    const float* __restrict__ pk_w, const float* __restrict__ pk_b,
    const float* __restrict__ pk_g, const float* __restrict__ pk_beta)
{
    __shared__ float sp[CIN * PTOK];
    for (int i = threadIdx.x; i < CIN * PTOK; i += 256) sp[i] = proxy[i];
    __syncthreads();
    const int k = threadIdx.x;
    for (int which = 0; which < 2; which++) {
        const float* w  = which ? pk_w : pq_w;
        const float* bb = which ? pk_b : pq_b;
        const float* g  = which ? pk_g : pq_g;
        const float* be = which ? pk_beta : pq_beta;
        float* dstp = which ? g_k2 : g_q1;
        float acc[PTOK];
#pragma unroll
        for (int p = 0; p < PTOK; p++) acc[p] = bb[k];
        for (int c = 0; c < CIN; c++) {
            float wv = w[(size_t)k * CIN + c];
#pragma unroll
            for (int p = 0; p < PTOK; p++) acc[p] = fmaf(wv, sp[c * PTOK + p], acc[p]);
        }
        float mean = 0.0f;
#pragma unroll
        for (int p = 0; p < PTOK; p++) mean += acc[p];
        mean *= (1.0f / PTOK);
        float var = 0.0f;
#pragma unroll
        for (int p = 0; p < PTOK; p++) { float d = acc[p] - mean; var += d * d; }
        var *= (1.0f / PTOK);
        float sc = g[k] * rsqrtf(var + BN_EPS);
        float sh = be[k] - mean * sc;
#pragma unroll
        for (int p = 0; p < PTOK; p++) {
            float z = acc[p] * sc + sh;
            dstp[k * PTOK + p] = (z > 0.0f) ? z : 0.01f * z;
        }
    }
}

// ---------------- stage 1 logits ----------------
__global__ __launch_bounds__(256) void kB1() {
    __shared__ float q1s[CK * PTOK];
    __shared__ float ks[CK], kh[CK];
    const int b = blockIdx.y;
    const int n = blockIdx.x * 256 + threadIdx.x;
    for (int i = threadIdx.x; i < CK * PTOK; i += 256) q1s[i] = g_q1[i];
    if (threadIdx.x < CK) { ks[threadIdx.x] = g_kscale[threadIdx.x]; kh[threadIdx.x] = g_kshift[threadIdx.x]; }
    __syncthreads();
    float acc[PTOK];
#pragma unroll
    for (int p = 0; p < PTOK; p++) acc[p] = 0.0f;
    const float* kp = g_k1 + (size_t)b * CK * NPIX + n;
    for (int k = 0; k < CK; k++) {
        float v = kp[(size_t)k * NPIX];
        v = fmaf(v, ks[k], kh[k]);
        v = (v > 0.0f) ? v : 0.01f * v;
#pragma unroll
        for (int p = 0; p < PTOK; p++) acc[p] = fmaf(q1s[k * PTOK + p], v, acc[p]);
    }
    float* out = g_logits1 + (size_t)b * PTOK * NPIX + n;
#pragma unroll
    for (int p = 0; p < PTOK; p++) out[(size_t)p * NPIX] = acc[p];
}

// ---------------- stage 1 softmax over N ----------------
__global__ __launch_bounds__(256) void kB2() {
    const int p = blockIdx.x, b = blockIdx.y;
    float* row = g_logits1 + ((size_t)b * PTOK + p) * NPIX;
    __shared__ float red[256];
    const int tid = threadIdx.x;
    float m = -3.4e38f;
    for (int i = tid; i < NPIX; i += 256) m = fmaxf(m, row[i]);
    red[tid] = m; __syncthreads();
    for (int off = 128; off > 0; off >>= 1) {
        if (tid < off) red[tid] = fmaxf(red[tid], red[tid + off]);
        __syncthreads();
    }
    float mx = red[0];
    __syncthreads();
    float s = 0.0f;
    for (int i = tid; i < NPIX; i += 256) s += expf(row[i] - mx);
    red[tid] = s; __syncthreads();
    for (int off = 128; off > 0; off >>= 1) {
        if (tid < off) red[tid] += red[tid + off];
        __syncthreads();
    }
    float inv = 1.0f / red[0];
    for (int i = tid; i < NPIX; i += 256) row[i] = expf(row[i] - mx) * inv;
}

// ---------------- stage 1 context part 1: y[b,p,c] = sum_n sim1[b,p,n] * x[b,c,n] ----------------
__global__ __launch_bounds__(256) void kB3x(const float* __restrict__ x) {
    __shared__ float xs[64 * 129];
    __shared__ float ss[PTOK * 129];
    const int nch = blockIdx.x;   // 0..7, 2048 n each
    const int ct  = blockIdx.y;   // 0..3, two 64-c tiles each
    const int b   = blockIdx.z;
    const int tid = threadIdx.x;
    const int tx16 = tid & 15;          // c group (4 each)
    const int ty   = (tid >> 4) & 3;    // p group (5 each)
    const int tz   = tid >> 6;          // nn quarter
    float acc[2][4][5];
#pragma unroll
    for (int u = 0; u < 2; u++)
#pragma unroll
        for (int i = 0; i < 4; i++)
#pragma unroll
            for (int j = 0; j < 5; j++) acc[u][i][j] = 0.0f;

    const float* sbase = g_logits1 + (size_t)b * PTOK * NPIX;

    for (int st = 0; st < 16; st++) {
        const int nb = nch * 2048 + st * 128;
#pragma unroll
        for (int sub = 0; sub < 2; sub++) {
            __syncthreads();
            if (sub == 0) {
                for (int s = tid; s < PTOK * 128; s += 256) {
                    int r = s >> 7, c = s & 127;
                    ss[r * 129 + c] = sbase[(size_t)r * NPIX + nb + c];
                }
            }
            const int c0 = (ct * 2 + sub) * 64;
            const float* xbase = x + ((size_t)b * CIN + c0) * NPIX;
            for (int s = tid; s < 64 * 128; s += 256) {
                int r = s >> 7, c = s & 127;
                xs[r * 129 + c] = xbase[(size_t)r * NPIX + nb + c];
            }
            __syncthreads();
#pragma unroll 4
            for (int nn = tz * 32; nn < tz * 32 + 32; nn++) {
                float sv[5];
#pragma unroll
                for (int j = 0; j < 5; j++) {
                    int p = ty * 5 + j;
                    sv[j] = (p < PTOK) ? ss[p * 129 + nn] : 0.0f;
                }
#pragma unroll
                for (int i = 0; i < 4; i++) {
                    float vv = xs[(tx16 * 4 + i) * 129 + nn];
#pragma unroll
                    for (int j = 0; j < 5; j++) acc[sub][i][j] = fmaf(vv, sv[j], acc[sub][i][j]);
                }
            }
        }
    }
#pragma unroll
    for (int sub = 0; sub < 2; sub++) {
        const int c0 = (ct * 2 + sub) * 64;
#pragma unroll
        for (int j = 0; j < 5; j++) {
            int p = ty * 5 + j;
            if (p < PTOK) {
#pragma unroll
                for (int i = 0; i < 4; i++)
                    atomicAdd(&g_y[((size_t)b * PTOK + p) * CIN + c0 + tx16 * 4 + i], acc[sub][i][j]);
            }
        }
    }
}

// ---------------- stage 1 context part 2: ctx[b,p,v] = sum_c fv_w[v,c]*y[b,p,c] + fv_b[v] ----------------
__global__ __launch_bounds__(256) void kCtx(const float* __restrict__ fvw, const float* __restrict__ fvb) {
    __shared__ float ys[PTOK * CIN];   // 38,912 B
    const int b = blockIdx.x;
    for (int i = threadIdx.x; i < PTOK * CIN; i += 256)
        ys[i] = g_y[(size_t)b * PTOK * CIN + i];
    __syncthreads();
    const int v = threadIdx.x;   // 256 v values
    float acc[PTOK];
    float bias = fvb[v];
#pragma unroll
    for (int p = 0; p < PTOK; p++) acc[p] = bias;
    const float* wrow = fvw + (size_t)v * CIN;
    for (int c = 0; c < CIN; c++) {
        float w = wrow[c];
#pragma unroll
        for (int p = 0; p < PTOK; p++) acc[p] = fmaf(w, ys[p * CIN + c], acc[p]);
    }
#pragma unroll
    for (int p = 0; p < PTOK; p++)
        g_ctx[((size_t)b * PTOK + p) * CV + v] = acc[p];
}

// ---------------- M precompute ----------------
__global__ __launch_bounds__(256) void kM(const float* __restrict__ Ww) {
    __shared__ float ctxs[PTOK * CV];
    const int b = blockIdx.x;
    for (int i = threadIdx.x; i < PTOK * CV; i += 256)
        ctxs[i] = g_ctx[(size_t)b * PTOK * CV + i];
    __syncthreads();
    for (int rep = 0; rep < 2; rep++) {
        int o = rep * 256 + threadIdx.x;
        float acc[PTOK];
#pragma unroll
        for (int p = 0; p < PTOK; p++) acc[p] = 0.0f;
        for (int v = 0; v < CV; v++) {
            float w = Ww[(size_t)o * CV + v];
#pragma unroll
            for (int p = 0; p < PTOK; p++) acc[p] = fmaf(w, ctxs[p * CV + v], acc[p]);
        }
        float* dstp = &g_M[((size_t)b * COUT + o) * 20];
#pragma unroll
        for (int p = 0; p < PTOK; p++) dstp[p] = acc[p];
        dstp[19] = 0.0f;
    }
}

// ---------------- stage 2: logits + softmax over P ----------------
__global__ __launch_bounds__(256) void kC1() {
    __shared__ float k2s[CK * PTOK];
    __shared__ float q2s[16 * 132];
    __shared__ float L[PTOK * 132];
    __shared__ float qs[CK], qh[CK];
    const int b = blockIdx.y;
    const int n0 = blockIdx.x * 128;
    const int tid = threadIdx.x;
    const int nl = tid & 127;
    const int half = tid >> 7;
    for (int i = tid; i < CK * PTOK; i += 256) k2s[i] = g_k2[i];
    if (tid < CK) { qs[tid] = g_qscale[tid]; qh[tid] = g_qshift[tid]; }
    __syncthreads();
    const int p0 = half * 10;
    const int nj = half ? 9 : 10;
    float acc[10];
#pragma unroll
    for (int j = 0; j < 10; j++) acc[j] = 0.0f;
    const float* qb = g_q2 + (size_t)b * CK * NPIX + n0;
    for (int k0 = 0; k0 < CK; k0 += 16) {
        for (int s = tid; s < 16 * 128; s += 256) {
            int r = s >> 7, c = s & 127;
            float v = qb[(size_t)(k0 + r) * NPIX + c];
            v = fmaf(v, qs[k0 + r], qh[k0 + r]);
            q2s[r * 132 + c] = (v > 0.0f) ? v : 0.01f * v;
        }
        __syncthreads();
#pragma unroll
        for (int kk = 0; kk < 16; kk++) {
            float v = q2s[kk * 132 + nl];
#pragma unroll
            for (int j = 0; j < 10; j++) {
                if (j < nj) acc[j] = fmaf(v, k2s[(k0 + kk) * PTOK + p0 + j], acc[j]);
            }
        }
        __syncthreads();
    }
    for (int j = 0; j < nj; j++) L[(p0 + j) * 132 + nl] = acc[j];
    __syncthreads();
    float mx = -3.4e38f;
#pragma unroll
    for (int p = 0; p < PTOK; p++) mx = fmaxf(mx, L[p * 132 + nl]);
    float ssum = 0.0f;
    float er[10];
#pragma unroll
    for (int p = 0; p < PTOK; p++) {
        float e = expf(L[p * 132 + nl] - mx);
        ssum += e;
        int j = p - p0;
        if (j >= 0 && j < nj) er[j] = e;
    }
    float inv = 1.0f / ssum;
    for (int j = 0; j < nj; j++)
        g_sim2[((size_t)b * PTOK + p0 + j) * NPIX + n0 + nl] = er[j] * inv;
}

// ---------------- epilogue ----------------
__global__ __launch_bounds__(256) void kC2(const float* __restrict__ Wb, float* __restrict__ out) {
    __shared__ __align__(16) float Ms[COUT * 20];
    __shared__ float wbs[COUT];
    const int b = blockIdx.y;
    const int n = blockIdx.x * 256 + threadIdx.x;
    for (int i = threadIdx.x; i < COUT * 20; i += 256) Ms[i] = g_M[(size_t)b * COUT * 20 + i];
    for (int i = threadIdx.x; i < COUT; i += 256) wbs[i] = Wb[i];
    __syncthreads();
    float sr[PTOK];
#pragma unroll
    for (int p = 0; p < PTOK; p++) sr[p] = g_sim2[((size_t)b * PTOK + p) * NPIX + n];
    float* ob = out + (size_t)b * COUT * NPIX + n;
#pragma unroll 2
    for (int o = 0; o < COUT; o++) {
        const float4* mp = reinterpret_cast<const float4*>(&Ms[o * 20]);
        float4 a0 = mp[0], a1 = mp[1], a2 = mp[2], a3 = mp[3];
        float a = wbs[o];
        a = fmaf(a0.x, sr[0], a);  a = fmaf(a0.y, sr[1], a);
        a = fmaf(a0.z, sr[2], a);  a = fmaf(a0.w, sr[3], a);
        a = fmaf(a1.x, sr[4], a);  a = fmaf(a1.y, sr[5], a);
        a = fmaf(a1.z, sr[6], a);  a = fmaf(a1.w, sr[7], a);
        a = fmaf(a2.x, sr[8], a);  a = fmaf(a2.y, sr[9], a);
        a = fmaf(a2.z, sr[10], a); a = fmaf(a2.w, sr[11], a);
        a = fmaf(a3.x, sr[12], a); a = fmaf(a3.y, sr[13], a);
        a = fmaf(a3.z, sr[14], a); a = fmaf(a3.w, sr[15], a);
        a = fmaf(Ms[o * 20 + 16], sr[16], a);
        a = fmaf(Ms[o * 20 + 17], sr[17], a);
        a = fmaf(Ms[o * 20 + 18], sr[18], a);
        ob[(size_t)o * NPIX] = a;
    }
}

// ---------------- launcher ----------------
extern "C" void kernel_launch(void* const* d_in, const int* in_sizes, int n_in,
                              void* d_out, int out_size) {
    const float* x        = (const float*)d_in[0];
    const float* proxy    = (const float*)d_in[1];
    const float* fk_w     = (const float*)d_in[2];
    const float* fk_b     = (const float*)d_in[3];
    const float* fk_g     = (const float*)d_in[4];
    const float* fk_beta  = (const float*)d_in[5];
    const float* fq_w     = (const float*)d_in[6];
    const float* fq_b     = (const float*)d_in[7];
    const float* fq_g     = (const float*)d_in[8];
    const float* fq_beta  = (const float*)d_in[9];
    const float* fv_w     = (const float*)d_in[10];
    const float* fv_b     = (const float*)d_in[11];
    const float* pq_w     = (const float*)d_in[12];
    const float* pq_b     = (const float*)d_in[13];
    const float* pq_g     = (const float*)d_in[14];
    const float* pq_beta  = (const float*)d_in[15];
    const float* pk_w     = (const float*)d_in[16];
    const float* pk_b     = (const float*)d_in[17];
    const float* pk_g     = (const float*)d_in[18];
    const float* pk_beta  = (const float*)d_in[19];
    const float* W_w      = (const float*)d_in[20];
    const float* W_b      = (const float*)d_in[21];
    float* out = (float*)d_out;

    kInit<<<312, 256>>>();
    kCvtW<<<W_BLK, 256>>>(fk_w, fq_w);
    kA2<<<dim3(128, 4, 8), 256>>>(x, fk_b, fq_b);
    kStats<<<dim3(512, 16), 256>>>();
    kFin<<<1, 512>>>(fk_g, fk_beta, fq_g, fq_beta);
    kT<<<1, 256>>>(proxy, pq_w, pq_b, pq_g, pq_beta, pk_w, pk_b, pk_g, pk_beta);
    kB1<<<dim3(64, 8), 256>>>();
    kB2<<<dim3(PTOK, 8), 256>>>();
    kB3x<<<dim3(8, 4, 8), 256>>>(x);
    kCtx<<<8, 256>>>(fv_w, fv_b);
    kM<<<8, 256>>>(W_w);
    kC1<<<dim3(128, 8), 256>>>();
    kC2<<<dim3(64, 8), 256>>>(W_b, out);
}

// round 8
// speedup vs baseline: 1.6268x; 1.1114x over previous
#include <cuda_runtime.h>
#include <cuda_fp16.h>
#include <math.h>
#include <stdint.h>

#define BATCH 8
#define CIN   512
#define CK    256
#define CV    256
#define COUT  512
#define NPIX  16384
#define PTOK  19
#define BN_EPS 1e-5f

// ---------------- scratch (static device memory; no allocations) ----------------
__device__ __align__(16) float g_k1[BATCH * CK * NPIX];
__device__ __align__(16) float g_q2[BATCH * CK * NPIX];
__device__ __align__(16) float g_logits1[BATCH * PTOK * NPIX];
__device__ __align__(16) float g_sim2[BATCH * PTOK * NPIX];
__device__ __align__(16) float g_y[BATCH * PTOK * CIN];
__device__ __align__(16) float g_ctx[BATCH * PTOK * CV];
__device__ __align__(16) float g_M[BATCH * COUT * 20];
__device__ float g_q1[CK * PTOK];
__device__ float g_k2[CK * PTOK];
__device__ float g_stat[4 * CK];
__device__ float g_kscale[CK], g_kshift[CK], g_qscale[CK], g_qshift[CK];
// fp16 weights (fk 256 rows | fq 256 rows), single precision-rounded copy
__device__ __align__(16) __half g_wh[512 * CIN];

// ---------------- init ----------------
__global__ void kInit() {
    int i = blockIdx.x * blockDim.x + threadIdx.x;
    if (i < 4 * CK) g_stat[i] = 0.0f;
    int j = i - 4 * CK;
    if (j >= 0 && j < BATCH * PTOK * CIN) g_y[j] = 0.0f;
}

// ---------------- fp16 hi/lo split helper (for X) ----------------
__device__ __forceinline__ void split1h(float v, unsigned short& h, unsigned short& l) {
    __half hb = __float2half_rn(v);
    h = __half_as_ushort(hb);
    l = __half_as_ushort(__float2half_rn(v - __half2float(hb)));
}

#define W_F4  (512 * CIN / 4)
#define W_BLK 32

// weight conversion: fp32 -> fp16 (fk | fq stacked)
__global__ __launch_bounds__(256) void kCvtW(
    const float* __restrict__ fkw, const float* __restrict__ fqw)
{
#pragma unroll
    for (int i = 0; i < 8; i++) {
        size_t fi = (size_t)blockIdx.x * 2048 + threadIdx.x + i * 256;
        if (fi >= W_F4) continue;
        size_t e = fi * 4;
        const float* src = (e < 131072) ? fkw : fqw;
        size_t off = e & 131071;
        float4 v = *(const float4*)&src[off];
        __half h0 = __float2half_rn(v.x), h1 = __float2half_rn(v.y);
        __half h2 = __float2half_rn(v.z), h3 = __float2half_rn(v.w);
        uint2 h;
        h.x = (uint32_t)__half_as_ushort(h0) | ((uint32_t)__half_as_ushort(h1) << 16);
        h.y = (uint32_t)__half_as_ushort(h2) | ((uint32_t)__half_as_ushort(h3) << 16);
        ((uint2*)g_wh)[fi] = h;
    }
}

// ---------------- Pass A: 2-pass fp16 tensor-core GEMM (fk + fq) ----------------
// y[m,n] = sum_c W[m,c] x[b,c,n] + bias[m] via W*Xh + W*Xl (fp32 accum).
// W pre-rounded to fp16; X split hi/lo fp16 in registers.
// CTA: 128m x 128n, K chunk 32, 8 warps (2m x 4n), warp tile 64m x 32n.
#define PITCH 17  // u32 words per 32-fp16 smem row (bank rotation)

#define MMA_F16(c, a, bf) asm volatile( \
    "mma.sync.aligned.m16n8k16.row.col.f32.f16.f16.f32 " \
    "{%0,%1,%2,%3},{%4,%5,%6,%7},{%8,%9},{%0,%1,%2,%3};" \
    : "+f"(c[0]), "+f"(c[1]), "+f"(c[2]), "+f"(c[3]) \
    : "r"(a[0]), "r"(a[1]), "r"(a[2]), "r"(a[3]), "r"(bf[0]), "r"(bf[1]))

__global__ __launch_bounds__(256) void kA2(
    const float* __restrict__ x,
    const float* __restrict__ fk_b, const float* __restrict__ fq_b)
{
    __shared__ uint32_t sA [128 * PITCH];
    __shared__ uint32_t sBh[128 * PITCH], sBl[128 * PITCH];

    const int t = threadIdx.x;
    const int lane = t & 31, warp = t >> 5;
    const int wm = warp >> 2, wn = warp & 3;
    const int n0 = blockIdx.x * 128;
    const int by = blockIdx.y;       // 0..3: fk0 fk1 fq0 fq1
    const int b  = blockIdx.z;
    const int mbase = by * 128;

    const float* bptr; float* dst;
    if (by < 2) { bptr = fk_b; dst = g_k1; }
    else        { bptr = fq_b; dst = g_q2; }
    const int chbase = (by & 1) * 128;

    const int am = t >> 1;                 // A row 0..127
    const int ak = (t & 1) * 16;           // A k sub-offset
    const __half* gA = g_wh + (size_t)(mbase + am) * CIN;
    const int bj = t & 15;                 // B n-block (8 wide)
    const int bk = (t >> 4) * 2;           // B k-pair
    const float* gX = x + ((size_t)b * CIN) * NPIX + n0 + bj * 8;

    float acc[4][4][4];
#pragma unroll
    for (int i = 0; i < 4; i++)
#pragma unroll
        for (int j = 0; j < 4; j++)
#pragma unroll
            for (int r = 0; r < 4; r++) acc[i][j][r] = 0.0f;

    uint4 rA0, rA1;
    float4 rx00, rx01, rx10, rx11;

#define LOADC(k0) do { \
    rA0 = *(const uint4*)(gA + (k0) + ak); \
    rA1 = *(const uint4*)(gA + (k0) + ak + 8); \
    rx00 = *(const float4*)(gX + (size_t)((k0) + bk) * NPIX); \
    rx01 = *(const float4*)(gX + (size_t)((k0) + bk) * NPIX + 4); \
    rx10 = *(const float4*)(gX + (size_t)((k0) + bk + 1) * NPIX); \
    rx11 = *(const float4*)(gX + (size_t)((k0) + bk + 1) * NPIX + 4); \
} while (0)

#define STOREC() do { \
    int wofs = am * PITCH + (ak >> 1); \
    const uint32_t* pa0 = (const uint32_t*)&rA0; const uint32_t* pa1 = (const uint32_t*)&rA1; \
    _Pragma("unroll") for (int i = 0; i < 4; i++) { \
        sA[wofs + i] = pa0[i]; sA[wofs + 4 + i] = pa1[i]; } \
    float bv0[8] = {rx00.x, rx00.y, rx00.z, rx00.w, rx01.x, rx01.y, rx01.z, rx01.w}; \
    float bv1[8] = {rx10.x, rx10.y, rx10.z, rx10.w, rx11.x, rx11.y, rx11.z, rx11.w}; \
    _Pragma("unroll") for (int i = 0; i < 8; i++) { \
        unsigned short h0, l0, h1, l1; \
        split1h(bv0[i], h0, l0); split1h(bv1[i], h1, l1); \
        sBh[(bj * 8 + i) * PITCH + (bk >> 1)] = (uint32_t)h0 | ((uint32_t)h1 << 16); \
        sBl[(bj * 8 + i) * PITCH + (bk >> 1)] = (uint32_t)l0 | ((uint32_t)l1 << 16); } \
} while (0)

    LOADC(0);
    STOREC();

    for (int c = 0; c < 16; c++) {
        __syncthreads();
        if (c < 15) LOADC((c + 1) * 32);
#pragma unroll
        for (int s = 0; s < 2; s++) {
            uint32_t a_f[4][4], b_h[4][2], b_l[4][2];
            const int aw = s * 8 + (lane & 3);
#pragma unroll
            for (int mf = 0; mf < 4; mf++) {
                int r = wm * 64 + mf * 16 + (lane >> 2);
                a_f[mf][0] = sA[r * PITCH + aw];
                a_f[mf][1] = sA[(r + 8) * PITCH + aw];
                a_f[mf][2] = sA[r * PITCH + aw + 4];
                a_f[mf][3] = sA[(r + 8) * PITCH + aw + 4];
            }
#pragma unroll
            for (int nf = 0; nf < 4; nf++) {
                int col = wn * 32 + nf * 8 + (lane >> 2);
                b_h[nf][0] = sBh[col * PITCH + aw];
                b_h[nf][1] = sBh[col * PITCH + aw + 4];
                b_l[nf][0] = sBl[col * PITCH + aw];
                b_l[nf][1] = sBl[col * PITCH + aw + 4];
            }
#pragma unroll
            for (int mf = 0; mf < 4; mf++)
#pragma unroll
                for (int nf = 0; nf < 4; nf++) {
                    MMA_F16(acc[mf][nf], a_f[mf], b_h[nf]);
                    MMA_F16(acc[mf][nf], a_f[mf], b_l[nf]);
                }
        }
        __syncthreads();
        if (c < 15) STOREC();
    }

    const size_t obase = (size_t)b * CK * NPIX;
#pragma unroll
    for (int mf = 0; mf < 4; mf++) {
        int r0 = chbase + wm * 64 + mf * 16 + (lane >> 2);
        float bias0 = bptr[r0], bias1 = bptr[r0 + 8];
#pragma unroll
        for (int nf = 0; nf < 4; nf++) {
            int n = n0 + wn * 32 + nf * 8 + (lane & 3) * 2;
            float2 v0 = make_float2(acc[mf][nf][0] + bias0, acc[mf][nf][1] + bias0);
            float2 v1 = make_float2(acc[mf][nf][2] + bias1, acc[mf][nf][3] + bias1);
            *(float2*)&dst[obase + (size_t)r0 * NPIX + n] = v0;
            *(float2*)&dst[obase + (size_t)(r0 + 8) * NPIX + n] = v1;
        }
    }
}

// ---------------- BN stats ----------------
__global__ __launch_bounds__(256) void kStats() {
    const int ch = blockIdx.x;
    const int chunk = blockIdx.y;
    const float* src = (ch < CK) ? g_k1 : g_q2;
    const int c = ch & (CK - 1);
    const int b = chunk >> 1;
    const int nh = (chunk & 1) * (NPIX / 2);
    const float* base = src + ((size_t)b * CK + c) * NPIX + nh;
    float sum = 0.0f, sq = 0.0f;
    for (int i = threadIdx.x; i < NPIX / 2; i += 256) {
        float v = base[i];
        sum += v; sq += v * v;
    }
    __shared__ float s1[256], s2[256];
    s1[threadIdx.x] = sum; s2[threadIdx.x] = sq;
    __syncthreads();
    for (int off = 128; off > 0; off >>= 1) {
        if (threadIdx.x < off) {
            s1[threadIdx.x] += s1[threadIdx.x + off];
            s2[threadIdx.x] += s2[threadIdx.x + off];
        }
        __syncthreads();
    }
    if (threadIdx.x == 0) {
        int b2 = (ch < CK) ? 0 : 2 * CK;
        atomicAdd(&g_stat[b2 + c], s1[0]);
        atomicAdd(&g_stat[b2 + CK + c], s2[0]);
    }
}

// ---------------- finalize BN ----------------
__global__ void kFin(const float* __restrict__ fk_g, const float* __restrict__ fk_beta,
                     const float* __restrict__ fq_g, const float* __restrict__ fq_beta) {
    int t = threadIdx.x;
    const float inv = 1.0f / (float)(BATCH * NPIX);
    if (t < CK) {
        float mean = g_stat[t] * inv;
        float var = g_stat[CK + t] * inv - mean * mean;
        float sc = fk_g[t] * rsqrtf(var + BN_EPS);
        g_kscale[t] = sc;
        g_kshift[t] = fk_beta[t] - mean * sc;
    } else if (t < 2 * CK) {
        int c = t - CK;
        float mean = g_stat[2 * CK + c] * inv;
        float var = g_stat[3 * CK + c] * inv - mean * mean;
        float sc = fq_g[c] * rsqrtf(var + BN_EPS);
        g_qscale[c] = sc;
        g_qshift[c] = fq_beta[c] - mean * sc;
    }
}

// ---------------- proxy-side projections ----------------
__global__ __launch_bounds__(256) void kT(
    const float* __restrict__ proxy,
    const float* __restrict__ pq_w, const float* __restrict__ pq_b,
    const float* __restrict__ pq_g, const float* __restrict__ pq_beta,
    const float* __restrict__ pk_w, const float* __restrict__ pk_b,
    const float* __restrict__ pk_g, const float* __restrict__ pk_beta)
{
    __shared__ float sp[CIN * PTOK];
    for (int i = threadIdx.x; i < CIN * PTOK; i += 256) sp[i] = proxy[i];
    __syncthreads();
    const int k = threadIdx.x;
    for (int which = 0; which < 2; which++) {
        const float* w  = which ? pk_w : pq_w;
        const float* bb = which ? pk_b : pq_b;
        const float* g  = which ? pk_g : pq_g;
        const float* be = which ? pk_beta : pq_beta;
        float* dstp = which ? g_k2 : g_q1;
        float acc[PTOK];
#pragma unroll
        for (int p = 0; p < PTOK; p++) acc[p] = bb[k];
        for (int c = 0; c < CIN; c++) {
            float wv = w[(size_t)k * CIN + c];
#pragma unroll
            for (int p = 0; p < PTOK; p++) acc[p] = fmaf(wv, sp[c * PTOK + p], acc[p]);
        }
        float mean = 0.0f;
#pragma unroll
        for (int p = 0; p < PTOK; p++) mean += acc[p];
        mean *= (1.0f / PTOK);
        float var = 0.0f;
#pragma unroll
        for (int p = 0; p < PTOK; p++) { float d = acc[p] - mean; var += d * d; }
        var *= (1.0f / PTOK);
        float sc = g[k] * rsqrtf(var + BN_EPS);
        float sh = be[k] - mean * sc;
#pragma unroll
        for (int p = 0; p < PTOK; p++) {
            float z = acc[p] * sc + sh;
            dstp[k * PTOK + p] = (z > 0.0f) ? z : 0.01f * z;
        }
    }
}

// ---------------- stage 1 logits ----------------
__global__ __launch_bounds__(256) void kB1() {
    __shared__ float q1s[CK * PTOK];
    __shared__ float ks[CK], kh[CK];
    const int b = blockIdx.y;
    const int n = blockIdx.x * 256 + threadIdx.x;
    for (int i = threadIdx.x; i < CK * PTOK; i += 256) q1s[i] = g_q1[i];
    if (threadIdx.x < CK) { ks[threadIdx.x] = g_kscale[threadIdx.x]; kh[threadIdx.x] = g_kshift[threadIdx.x]; }
    __syncthreads();
    float acc[PTOK];
#pragma unroll
    for (int p = 0; p < PTOK; p++) acc[p] = 0.0f;
    const float* kp = g_k1 + (size_t)b * CK * NPIX + n;
    for (int k = 0; k < CK; k++) {
        float v = kp[(size_t)k * NPIX];
        v = fmaf(v, ks[k], kh[k]);
        v = (v > 0.0f) ? v : 0.01f * v;
#pragma unroll
        for (int p = 0; p < PTOK; p++) acc[p] = fmaf(q1s[k * PTOK + p], v, acc[p]);
    }
    float* out = g_logits1 + (size_t)b * PTOK * NPIX + n;
#pragma unroll
    for (int p = 0; p < PTOK; p++) out[(size_t)p * NPIX] = acc[p];
}

// ---------------- stage 1 softmax over N ----------------
__global__ __launch_bounds__(256) void kB2() {
    const int p = blockIdx.x, b = blockIdx.y;
    float* row = g_logits1 + ((size_t)b * PTOK + p) * NPIX;
    __shared__ float red[256];
    const int tid = threadIdx.x;
    float m = -3.4e38f;
    for (int i = tid; i < NPIX; i += 256) m = fmaxf(m, row[i]);
    red[tid] = m; __syncthreads();
    for (int off = 128; off > 0; off >>= 1) {
        if (tid < off) red[tid] = fmaxf(red[tid], red[tid + off]);
        __syncthreads();
    }
    float mx = red[0];
    __syncthreads();
    float s = 0.0f;
    for (int i = tid; i < NPIX; i += 256) s += expf(row[i] - mx);
    red[tid] = s; __syncthreads();
    for (int off = 128; off > 0; off >>= 1) {
        if (tid < off) red[tid] += red[tid + off];
        __syncthreads();
    }
    float inv = 1.0f / red[0];
    for (int i = tid; i < NPIX; i += 256) row[i] = expf(row[i] - mx) * inv;
}

// ---------------- stage 1 context part 1 ----------------
__global__ __launch_bounds__(256) void kB3x(const float* __restrict__ x) {
    __shared__ float xs[64 * 129];
    __shared__ float ss[PTOK * 129];
    const int nch = blockIdx.x;
    const int ct  = blockIdx.y;
    const int b   = blockIdx.z;
    const int tid = threadIdx.x;
    const int tx16 = tid & 15;
    const int ty   = (tid >> 4) & 3;
    const int tz   = tid >> 6;
    float acc[2][4][5];
#pragma unroll
    for (int u = 0; u < 2; u++)
#pragma unroll
        for (int i = 0; i < 4; i++)
#pragma unroll
            for (int j = 0; j < 5; j++) acc[u][i][j] = 0.0f;

    const float* sbase = g_logits1 + (size_t)b * PTOK * NPIX;

    for (int st = 0; st < 16; st++) {
        const int nb = nch * 2048 + st * 128;
#pragma unroll
        for (int sub = 0; sub < 2; sub++) {
            __syncthreads();
            if (sub == 0) {
                for (int s = tid; s < PTOK * 128; s += 256) {
                    int r = s >> 7, c = s & 127;
                    ss[r * 129 + c] = sbase[(size_t)r * NPIX + nb + c];
                }
            }
            const int c0 = (ct * 2 + sub) * 64;
            const float* xbase = x + ((size_t)b * CIN + c0) * NPIX;
            for (int s = tid; s < 64 * 128; s += 256) {
                int r = s >> 7, c = s & 127;
                xs[r * 129 + c] = xbase[(size_t)r * NPIX + nb + c];
            }
            __syncthreads();
#pragma unroll 4
            for (int nn = tz * 32; nn < tz * 32 + 32; nn++) {
                float sv[5];
#pragma unroll
                for (int j = 0; j < 5; j++) {
                    int p = ty * 5 + j;
                    sv[j] = (p < PTOK) ? ss[p * 129 + nn] : 0.0f;
                }
#pragma unroll
                for (int i = 0; i < 4; i++) {
                    float vv = xs[(tx16 * 4 + i) * 129 + nn];
#pragma unroll
                    for (int j = 0; j < 5; j++) acc[sub][i][j] = fmaf(vv, sv[j], acc[sub][i][j]);
                }
            }
        }
    }
#pragma unroll
    for (int sub = 0; sub < 2; sub++) {
        const int c0 = (ct * 2 + sub) * 64;
#pragma unroll
        for (int j = 0; j < 5; j++) {
            int p = ty * 5 + j;
            if (p < PTOK) {
#pragma unroll
                for (int i = 0; i < 4; i++)
                    atomicAdd(&g_y[((size_t)b * PTOK + p) * CIN + c0 + tx16 * 4 + i], acc[sub][i][j]);
            }
        }
    }
}

// ---------------- stage 1 context part 2 ----------------
__global__ __launch_bounds__(256) void kCtx(const float* __restrict__ fvw, const float* __restrict__ fvb) {
    __shared__ float ys[PTOK * CIN];
    const int b = blockIdx.x;
    for (int i = threadIdx.x; i < PTOK * CIN; i += 256)
        ys[i] = g_y[(size_t)b * PTOK * CIN + i];
    __syncthreads();
    const int v = threadIdx.x;
    float acc[PTOK];
    float bias = fvb[v];
#pragma unroll
    for (int p = 0; p < PTOK; p++) acc[p] = bias;
    const float* wrow = fvw + (size_t)v * CIN;
    for (int c = 0; c < CIN; c++) {
        float w = wrow[c];
#pragma unroll
        for (int p = 0; p < PTOK; p++) acc[p] = fmaf(w, ys[p * CIN + c], acc[p]);
    }
#pragma unroll
    for (int p = 0; p < PTOK; p++)
        g_ctx[((size_t)b * PTOK + p) * CV + v] = acc[p];
}

// ---------------- M precompute ----------------
__global__ __launch_bounds__(256) void kM(const float* __restrict__ Ww) {
    __shared__ float ctxs[PTOK * CV];
    const int b = blockIdx.x;
    for (int i = threadIdx.x; i < PTOK * CV; i += 256)
        ctxs[i] = g_ctx[(size_t)b * PTOK * CV + i];
    __syncthreads();
    for (int rep = 0; rep < 2; rep++) {
        int o = rep * 256 + threadIdx.x;
        float acc[PTOK];
#pragma unroll
        for (int p = 0; p < PTOK; p++) acc[p] = 0.0f;
        for (int v = 0; v < CV; v++) {
            float w = Ww[(size_t)o * CV + v];
#pragma unroll
            for (int p = 0; p < PTOK; p++) acc[p] = fmaf(w, ctxs[p * CV + v], acc[p]);
        }
        float* dstp = &g_M[((size_t)b * COUT + o) * 20];
#pragma unroll
        for (int p = 0; p < PTOK; p++) dstp[p] = acc[p];
        dstp[19] = 0.0f;
    }
}

// ---------------- stage 2: logits + softmax over P ----------------
__global__ __launch_bounds__(256) void kC1() {
    __shared__ float k2s[CK * PTOK];
    __shared__ float q2s[16 * 132];
    __shared__ float L[PTOK * 132];
    __shared__ float qs[CK], qh[CK];
    const int b = blockIdx.y;
    const int n0 = blockIdx.x * 128;
    const int tid = threadIdx.x;
    const int nl = tid & 127;
    const int half = tid >> 7;
    for (int i = tid; i < CK * PTOK; i += 256) k2s[i] = g_k2[i];
    if (tid < CK) { qs[tid] = g_qscale[tid]; qh[tid] = g_qshift[tid]; }
    __syncthreads();
    const int p0 = half * 10;
    const int nj = half ? 9 : 10;
    float acc[10];
#pragma unroll
    for (int j = 0; j < 10; j++) acc[j] = 0.0f;
    const float* qb = g_q2 + (size_t)b * CK * NPIX + n0;
    for (int k0 = 0; k0 < CK; k0 += 16) {
        for (int s = tid; s < 16 * 128; s += 256) {
            int r = s >> 7, c = s & 127;
            float v = qb[(size_t)(k0 + r) * NPIX + c];
            v = fmaf(v, qs[k0 + r], qh[k0 + r]);
            q2s[r * 132 + c] = (v > 0.0f) ? v : 0.01f * v;
        }
        __syncthreads();
#pragma unroll
        for (int kk = 0; kk < 16; kk++) {
            float v = q2s[kk * 132 + nl];
#pragma unroll
            for (int j = 0; j < 10; j++) {
                if (j < nj) acc[j] = fmaf(v, k2s[(k0 + kk) * PTOK + p0 + j], acc[j]);
            }
        }
        __syncthreads();
    }
    for (int j = 0; j < nj; j++) L[(p0 + j) * 132 + nl] = acc[j];
    __syncthreads();
    float mx = -3.4e38f;
#pragma unroll
    for (int p = 0; p < PTOK; p++) mx = fmaxf(mx, L[p * 132 + nl]);
    float ssum = 0.0f;
    float er[10];
#pragma unroll
    for (int p = 0; p < PTOK; p++) {
        float e = expf(L[p * 132 + nl] - mx);
        ssum += e;
        int j = p - p0;
        if (j >= 0 && j < nj) er[j] = e;
    }
    float inv = 1.0f / ssum;
    for (int j = 0; j < nj; j++)
        g_sim2[((size_t)b * PTOK + p0 + j) * NPIX + n0 + nl] = er[j] * inv;
}

// ---------------- epilogue ----------------
__global__ __launch_bounds__(256) void kC2(const float* __restrict__ Wb, float* __restrict__ out) {
    __shared__ __align__(16) float Ms[COUT * 20];
    __shared__ float wbs[COUT];
    const int b = blockIdx.y;
    const int n = blockIdx.x * 256 + threadIdx.x;
    for (int i = threadIdx.x; i < COUT * 20; i += 256) Ms[i] = g_M[(size_t)b * COUT * 20 + i];
    for (int i = threadIdx.x; i < COUT; i += 256) wbs[i] = Wb[i];
    __syncthreads();
    float sr[PTOK];
#pragma unroll
    for (int p = 0; p < PTOK; p++) sr[p] = g_sim2[((size_t)b * PTOK + p) * NPIX + n];
    float* ob = out + (size_t)b * COUT * NPIX + n;
#pragma unroll 2
    for (int o = 0; o < COUT; o++) {
        const float4* mp = reinterpret_cast<const float4*>(&Ms[o * 20]);
        float4 a0 = mp[0], a1 = mp[1], a2 = mp[2], a3 = mp[3];
        float a = wbs[o];
        a = fmaf(a0.x, sr[0], a);  a = fmaf(a0.y, sr[1], a);
        a = fmaf(a0.z, sr[2], a);  a = fmaf(a0.w, sr[3], a);
        a = fmaf(a1.x, sr[4], a);  a = fmaf(a1.y, sr[5], a);
        a = fmaf(a1.z, sr[6], a);  a = fmaf(a1.w, sr[7], a);
        a = fmaf(a2.x, sr[8], a);  a = fmaf(a2.y, sr[9], a);
        a = fmaf(a2.z, sr[10], a); a = fmaf(a2.w, sr[11], a);
        a = fmaf(a3.x, sr[12], a); a = fmaf(a3.y, sr[13], a);
        a = fmaf(a3.z, sr[14], a); a = fmaf(a3.w, sr[15], a);
        a = fmaf(Ms[o * 20 + 16], sr[16], a);
        a = fmaf(Ms[o * 20 + 17], sr[17], a);
        a = fmaf(Ms[o * 20 + 18], sr[18], a);
        ob[(size_t)o * NPIX] = a;
    }
}

// ---------------- launcher ----------------
extern "C" void kernel_launch(void* const* d_in, const int* in_sizes, int n_in,
                              void* d_out, int out_size) {
    const float* x        = (const float*)d_in[0];
    const float* proxy    = (const float*)d_in[1];
    const float* fk_w     = (const float*)d_in[2];
    const float* fk_b     = (const float*)d_in[3];
    const float* fk_g     = (const float*)d_in[4];
    const float* fk_beta  = (const float*)d_in[5];
    const float* fq_w     = (const float*)d_in[6];
    const float* fq_b     = (const float*)d_in[7];
    const float* fq_g     = (const float*)d_in[8];
    const float* fq_beta  = (const float*)d_in[9];
    const float* fv_w     = (const float*)d_in[10];
    const float* fv_b     = (const float*)d_in[11];
    const float* pq_w     = (const float*)d_in[12];
    const float* pq_b     = (const float*)d_in[13];
    const float* pq_g     = (const float*)d_in[14];
    const float* pq_beta  = (const float*)d_in[15];
    const float* pk_w     = (const float*)d_in[16];
    const float* pk_b     = (const float*)d_in[17];
    const float* pk_g     = (const float*)d_in[18];
    const float* pk_beta  = (const float*)d_in[19];
    const float* W_w      = (const float*)d_in[20];
    const float* W_b      = (const float*)d_in[21];
    float* out = (float*)d_out;

    kInit<<<312, 256>>>();
    kCvtW<<<W_BLK, 256>>>(fk_w, fq_w);
    kA2<<<dim3(128, 4, 8), 256>>>(x, fk_b, fq_b);
    kStats<<<dim3(512, 16), 256>>>();
    kFin<<<1, 512>>>(fk_g, fk_beta, fq_g, fq_beta);
    kT<<<1, 256>>>(proxy, pq_w, pq_b, pq_g, pq_beta, pk_w, pk_b, pk_g, pk_beta);
    kB1<<<dim3(64, 8), 256>>>();
    kB2<<<dim3(PTOK, 8), 256>>>();
    kB3x<<<dim3(8, 4, 8), 256>>>(x);
    kCtx<<<8, 256>>>(fv_w, fv_b);
    kM<<<8, 256>>>(W_w);
    kC1<<<dim3(128, 8), 256>>>();
    kC2<<<dim3(64, 8), 256>>>(W_b, out);
}